// round 3
// baseline (speedup 1.0000x reference)
#include <cuda_runtime.h>
#include <cuda_bf16.h>
#include <stdint.h>
#include <math.h>

#define N_TOK 4096
#define DIM   1024
#define HID   4096
#define NEXP  8
#define NSLOT 8192
#define SLOT_PAD (NSLOT + 128)

// ---------------- scratch (__device__ globals only) ----------------
__device__ int g_counts[NEXP];
__device__ int g_cursor[NEXP];
__device__ int g_offsets[NEXP + 1];
__device__ int g_tg_e[N_TOK * 2];
__device__ float g_tg_w[N_TOK * 2];
__device__ int g_slot_token[NSLOT];
__device__ int g_tok_slot[N_TOK * 2];

__device__ __align__(16) __nv_bfloat16 g_Xg_hi[(size_t)SLOT_PAD * DIM];
__device__ __align__(16) __nv_bfloat16 g_Xg_lo[(size_t)SLOT_PAD * DIM];
__device__ __align__(16) __nv_bfloat16 g_Hg_hi[(size_t)SLOT_PAD * HID];
__device__ __align__(16) __nv_bfloat16 g_Hg_lo[(size_t)SLOT_PAD * HID];
__device__ __align__(16) __nv_bfloat16 g_W1t_hi[(size_t)NEXP * HID * DIM]; // [e][h][d]
__device__ __align__(16) __nv_bfloat16 g_W1t_lo[(size_t)NEXP * HID * DIM];
__device__ __align__(16) __nv_bfloat16 g_W2t_hi[(size_t)NEXP * DIM * HID]; // [e][d][h]
__device__ __align__(16) __nv_bfloat16 g_W2t_lo[(size_t)NEXP * DIM * HID];
__device__ __align__(16) float g_y[(size_t)SLOT_PAD * DIM];

// ---------------- helpers ----------------
__device__ __forceinline__ uint32_t smem_u32(const void* p) {
    uint32_t a;
    asm("{ .reg .u64 t; cvta.to.shared.u64 t, %1; cvt.u32.u64 %0, t; }" : "=r"(a) : "l"(p));
    return a;
}
__device__ __forceinline__ uint32_t pack2(__nv_bfloat16 a, __nv_bfloat16 b) {
    return (uint32_t)__bfloat16_as_ushort(a) | ((uint32_t)__bfloat16_as_ushort(b) << 16);
}
__device__ __forceinline__ void cp16(uint32_t dst, const void* src) {
    asm volatile("cp.async.cg.shared.global [%0], [%1], 16;" :: "r"(dst), "l"(src));
}
#define CP_COMMIT() asm volatile("cp.async.commit_group;" ::: "memory")
#define CP_WAIT1()  asm volatile("cp.async.wait_group 1;" ::: "memory")

__device__ __forceinline__ void ldm4(uint32_t* r, uint32_t addr) {
    asm volatile("ldmatrix.sync.aligned.m8n8.x4.shared.b16 {%0,%1,%2,%3}, [%4];"
                 : "=r"(r[0]), "=r"(r[1]), "=r"(r[2]), "=r"(r[3]) : "r"(addr));
}
__device__ __forceinline__ void mma16816(float* c, const uint32_t* a, const uint32_t* b) {
    asm volatile("mma.sync.aligned.m16n8k16.row.col.f32.bf16.bf16.f32 "
                 "{%0,%1,%2,%3}, {%4,%5,%6,%7}, {%8,%9}, {%0,%1,%2,%3};"
                 : "+f"(c[0]), "+f"(c[1]), "+f"(c[2]), "+f"(c[3])
                 : "r"(a[0]), "r"(a[1]), "r"(a[2]), "r"(a[3]), "r"(b[0]), "r"(b[1]));
}

// ---------------- 1) gating ----------------
__global__ void k_reset() { if (threadIdx.x < NEXP) g_counts[threadIdx.x] = 0; }

__global__ void k_gate(const float* __restrict__ x, const float* __restrict__ Wg,
                       const float* __restrict__ bg) {
    int wid = threadIdx.x >> 5, lane = threadIdx.x & 31;
    int n = blockIdx.x * 8 + wid;
    float acc[8] = {0,0,0,0,0,0,0,0};
    const float4* wg4 = (const float4*)Wg;
    for (int k = lane; k < DIM; k += 32) {
        float xv = x[(size_t)n * DIM + k];
        float4 w0 = wg4[k * 2], w1 = wg4[k * 2 + 1];
        acc[0] = fmaf(xv, w0.x, acc[0]); acc[1] = fmaf(xv, w0.y, acc[1]);
        acc[2] = fmaf(xv, w0.z, acc[2]); acc[3] = fmaf(xv, w0.w, acc[3]);
        acc[4] = fmaf(xv, w1.x, acc[4]); acc[5] = fmaf(xv, w1.y, acc[5]);
        acc[6] = fmaf(xv, w1.z, acc[6]); acc[7] = fmaf(xv, w1.w, acc[7]);
    }
    #pragma unroll
    for (int e = 0; e < 8; e++)
        #pragma unroll
        for (int off = 16; off; off >>= 1)
            acc[e] += __shfl_down_sync(0xffffffffu, acc[e], off);
    if (lane == 0) {
        float s[8];
        #pragma unroll
        for (int e = 0; e < 8; e++) s[e] = acc[e] + bg[e];
        int e0 = 0; float s0 = s[0];
        #pragma unroll
        for (int e = 1; e < 8; e++) if (s[e] > s0) { s0 = s[e]; e0 = e; }
        int e1 = -1; float s1 = -3.0e38f;
        #pragma unroll
        for (int e = 0; e < 8; e++) if (e != e0 && s[e] > s1) { s1 = s[e]; e1 = e; }
        float t = expf(s1 - s0);
        g_tg_e[n * 2] = e0; g_tg_e[n * 2 + 1] = e1;
        g_tg_w[n * 2] = 1.f / (1.f + t); g_tg_w[n * 2 + 1] = t / (1.f + t);
        atomicAdd(&g_counts[e0], 1);
        atomicAdd(&g_counts[e1], 1);
    }
}

__global__ void k_scan() {
    int o = 0;
    for (int e = 0; e < NEXP; e++) { g_offsets[e] = o; o += g_counts[e]; g_cursor[e] = 0; }
    g_offsets[NEXP] = o;
}

__global__ void k_scatter() {
    int n = blockIdx.x * blockDim.x + threadIdx.x;
    if (n < N_TOK) {
        #pragma unroll
        for (int i = 0; i < 2; i++) {
            int e = g_tg_e[n * 2 + i];
            int slot = g_offsets[e] + atomicAdd(&g_cursor[e], 1);
            g_slot_token[slot] = n;
            g_tok_slot[n * 2 + i] = slot;
        }
    }
}

// ---------------- 2) gather x, bf16 hi/lo split ----------------
__global__ void k_gather(const float* __restrict__ x) {
    int s = blockIdx.x, t = threadIdx.x;
    int n = g_slot_token[s];
    const float4* xr = (const float4*)(x + (size_t)n * DIM);
    float4 a = xr[t * 2], b = xr[t * 2 + 1];
    float v[8] = {a.x, a.y, a.z, a.w, b.x, b.y, b.z, b.w};
    uint32_t ph[4], pl[4];
    #pragma unroll
    for (int i = 0; i < 4; i++) {
        __nv_bfloat16 h0 = __float2bfloat16(v[2*i]), h1 = __float2bfloat16(v[2*i+1]);
        ph[i] = pack2(h0, h1);
        pl[i] = pack2(__float2bfloat16(v[2*i]   - __bfloat162float(h0)),
                      __float2bfloat16(v[2*i+1] - __bfloat162float(h1)));
    }
    *(uint4*)(g_Xg_hi + (size_t)s * DIM + t * 8) = *(uint4*)ph;
    *(uint4*)(g_Xg_lo + (size_t)s * DIM + t * 8) = *(uint4*)pl;
}

// ---------------- 3) weight transpose + split: in[e][R][C] -> out[e][C][R] ----------------
__global__ void k_prep_w(const float* __restrict__ in, int R, int C, int which) {
    __nv_bfloat16* oh = which ? g_W2t_hi : g_W1t_hi;
    __nv_bfloat16* ol = which ? g_W2t_lo : g_W1t_lo;
    __shared__ float tile[32][33];
    int e = blockIdx.z;
    int r0 = blockIdx.y * 32, c0 = blockIdx.x * 32;
    int tx = threadIdx.x, ty = threadIdx.y;
    const float* ip = in + (size_t)e * R * C;
    #pragma unroll
    for (int j = 0; j < 32; j += 8)
        tile[ty + j][tx] = ip[(size_t)(r0 + ty + j) * C + c0 + tx];
    __syncthreads();
    size_t ob = (size_t)e * R * C;
    #pragma unroll
    for (int j = 0; j < 32; j += 8) {
        float v = tile[tx][ty + j];
        __nv_bfloat16 h = __float2bfloat16(v);
        size_t oi = ob + (size_t)(c0 + ty + j) * R + r0 + tx;
        oh[oi] = h;
        ol[oi] = __float2bfloat16(v - __bfloat162float(h));
    }
}

// ---------------- 4) grouped GEMM (mma.sync bf16x3): 128x128x32, 3-stage cp.async ----------------
// smem per stage: Ah | Al | Bh | Bl, each 128 rows * 80B (64B data + 16B pad)
#define ROWB   80
#define T_AH   0
#define T_AL   10240
#define T_BH   20480
#define T_BL   30720
#define STAGEB 40960
#define NSTAGE 3
#define SMEM_BYTES (STAGEB * NSTAGE)

template <int KDIM, bool FFN1>
__global__ void __launch_bounds__(256) k_gemm(const float* __restrict__ bias_all) {
    constexpr int NTOT = FFN1 ? HID : DIM;
    constexpr int NCHUNK = KDIM / 32;
    extern __shared__ char sm[];
    uint32_t smb = smem_u32(sm);

    int e = blockIdx.z;
    int off_e = g_offsets[e];
    int cnt = g_offsets[e + 1] - off_e;
    int bm = blockIdx.y;
    if (bm * 128 >= cnt) return;
    int n_base = blockIdx.x * 128;
    int slot0 = off_e + bm * 128;

    int t = threadIdx.x;
    int warp = t >> 5, lane = t & 31;
    int wm = (warp & 3) * 32;      // warp M offset
    int wn = (warp >> 2) * 64;     // warp N offset

    const __nv_bfloat16* Ah = (FFN1 ? g_Xg_hi : g_Hg_hi) + (size_t)slot0 * KDIM;
    const __nv_bfloat16* Al = (FFN1 ? g_Xg_lo : g_Hg_lo) + (size_t)slot0 * KDIM;
    const __nv_bfloat16* Bh = (FFN1 ? g_W1t_hi : g_W2t_hi) + ((size_t)e * NTOT + n_base) * KDIM;
    const __nv_bfloat16* Bl = (FFN1 ? g_W1t_lo : g_W2t_lo) + ((size_t)e * NTOT + n_base) * KDIM;
    const float* bias = bias_all + (size_t)e * NTOT;

    // per-thread load slots: i in [0,512) per tensor, 2 per thread
    int li0 = t, li1 = t + 256;

    auto load_stage = [&](int stage, int ch) {
        uint32_t sb = smb + stage * STAGEB;
        int k0 = ch * 32;
        #pragma unroll
        for (int rep = 0; rep < 2; rep++) {
            int i = rep ? li1 : li0;
            int row = i >> 2, c = i & 3;
            uint32_t d = (uint32_t)(row * ROWB + c * 16);
            size_t src = (size_t)row * KDIM + k0 + c * 8;
            cp16(sb + T_AH + d, Ah + src);
            cp16(sb + T_AL + d, Al + src);
            cp16(sb + T_BH + d, Bh + src);
            cp16(sb + T_BL + d, Bl + src);
        }
    };

    // prefetch
    load_stage(0, 0); CP_COMMIT();
    load_stage(1, 1); CP_COMMIT();

    float acc[2][8][4];
    #pragma unroll
    for (int mt = 0; mt < 2; mt++)
        #pragma unroll
        for (int nt = 0; nt < 8; nt++)
            #pragma unroll
            for (int i = 0; i < 4; i++) acc[mt][nt][i] = 0.f;

    // ldmatrix per-thread address components
    int g = lane >> 3, r8 = lane & 7;
    // A x4: m_off=(g&1)*8, k_off=(g>>1)*8
    uint32_t aRow = (uint32_t)(wm + r8 + (g & 1) * 8);
    uint32_t aK   = (uint32_t)((g >> 1) * 8);
    // B x4: n_off=(g>>1)*8, k_off=(g&1)*8
    uint32_t bRow = (uint32_t)(wn + r8 + (g >> 1) * 8);
    uint32_t bK   = (uint32_t)((g & 1) * 8);

    for (int ch = 0; ch < NCHUNK; ch++) {
        CP_WAIT1();
        __syncthreads();
        if (ch + 2 < NCHUNK) load_stage((ch + 2) % NSTAGE, ch + 2);
        CP_COMMIT();

        uint32_t sb = smb + (ch % NSTAGE) * STAGEB;
        #pragma unroll
        for (int kc = 0; kc < 2; kc++) {
            uint32_t a_hi[2][4], a_lo[2][4];
            #pragma unroll
            for (int mt = 0; mt < 2; mt++) {
                uint32_t ad = sb + (aRow + mt * 16) * ROWB + (kc * 16 + aK) * 2;
                ldm4(a_hi[mt], ad + T_AH);
                ldm4(a_lo[mt], ad + T_AL);
            }
            uint32_t b_hi[4][4], b_lo[4][4];
            #pragma unroll
            for (int np = 0; np < 4; np++) {
                uint32_t bd = sb + (bRow + np * 16) * ROWB + (kc * 16 + bK) * 2;
                ldm4(b_hi[np], bd + T_BH);
                ldm4(b_lo[np], bd + T_BL);
            }
            #pragma unroll
            for (int mt = 0; mt < 2; mt++)
                #pragma unroll
                for (int nt = 0; nt < 8; nt++) {
                    const uint32_t* bh = &b_hi[nt >> 1][(nt & 1) * 2];
                    const uint32_t* bl = &b_lo[nt >> 1][(nt & 1) * 2];
                    mma16816(acc[mt][nt], a_hi[mt], bh);
                    mma16816(acc[mt][nt], a_hi[mt], bl);
                    mma16816(acc[mt][nt], a_lo[mt], bh);
                }
        }
        __syncthreads();
    }

    // epilogue
    int rlo = lane >> 2;            // 0..7
    int cpair = (lane & 3) * 2;     // 0,2,4,6
    #pragma unroll
    for (int mt = 0; mt < 2; mt++) {
        #pragma unroll
        for (int half = 0; half < 2; half++) {
            int m = bm * 128 + wm + mt * 16 + half * 8 + rlo;
            if (m >= cnt) continue;
            int slot = off_e + m;
            #pragma unroll
            for (int nt = 0; nt < 8; nt++) {
                int col = n_base + wn + nt * 8 + cpair;
                float v0 = acc[mt][nt][half * 2]     + bias[col];
                float v1 = acc[mt][nt][half * 2 + 1] + bias[col + 1];
                if (FFN1) {
                    v0 = fmaxf(v0, 0.f); v1 = fmaxf(v1, 0.f);
                    __nv_bfloat16 h0 = __float2bfloat16(v0), h1 = __float2bfloat16(v1);
                    size_t o = (size_t)slot * HID + col;
                    *(uint32_t*)(g_Hg_hi + o) = pack2(h0, h1);
                    *(uint32_t*)(g_Hg_lo + o) =
                        pack2(__float2bfloat16(v0 - __bfloat162float(h0)),
                              __float2bfloat16(v1 - __bfloat162float(h1)));
                } else {
                    size_t o = (size_t)slot * DIM + col;
                    float2 f2; f2.x = v0; f2.y = v1;
                    *(float2*)(g_y + o) = f2;
                }
            }
        }
    }
}

// ---------------- 5) combine ----------------
__global__ void k_combine(float* __restrict__ out) {
    int n = blockIdx.x, t = threadIdx.x;
    int s0 = g_tok_slot[n * 2], s1 = g_tok_slot[n * 2 + 1];
    float w0 = g_tg_w[n * 2], w1 = g_tg_w[n * 2 + 1];
    float4 a = ((const float4*)(g_y + (size_t)s0 * DIM))[t];
    float4 b = ((const float4*)(g_y + (size_t)s1 * DIM))[t];
    float4 o;
    o.x = w0 * a.x + w1 * b.x; o.y = w0 * a.y + w1 * b.y;
    o.z = w0 * a.z + w1 * b.z; o.w = w0 * a.w + w1 * b.w;
    ((float4*)(out + (size_t)n * DIM))[t] = o;
}

// ---------------- launch ----------------
extern "C" void kernel_launch(void* const* d_in, const int* in_sizes, int n_in,
                              void* d_out, int out_size) {
    const float* x  = (const float*)d_in[0];
    const float* Wg = (const float*)d_in[1];
    const float* bg = (const float*)d_in[2];
    const float* W1 = (const float*)d_in[3];
    const float* b1 = (const float*)d_in[4];
    const float* W2 = (const float*)d_in[5];
    const float* b2 = (const float*)d_in[6];
    float* out = (float*)d_out;

    cudaFuncSetAttribute(k_gemm<DIM, true>,  cudaFuncAttributeMaxDynamicSharedMemorySize, SMEM_BYTES);
    cudaFuncSetAttribute(k_gemm<HID, false>, cudaFuncAttributeMaxDynamicSharedMemorySize, SMEM_BYTES);

    k_reset<<<1, 32>>>();
    k_gate<<<N_TOK / 8, 256>>>(x, Wg, bg);
    k_scan<<<1, 1>>>();
    k_scatter<<<N_TOK / 256, 256>>>();
    k_gather<<<NSLOT, 128>>>(x);
    k_prep_w<<<dim3(HID / 32, DIM / 32, NEXP), dim3(32, 8)>>>(W1, DIM, HID, 0);
    k_prep_w<<<dim3(DIM / 32, HID / 32, NEXP), dim3(32, 8)>>>(W2, HID, DIM, 1);
    k_gemm<DIM, true><<<dim3(HID / 128, NSLOT / 128, NEXP), 256, SMEM_BYTES>>>(b1);
    k_gemm<HID, false><<<dim3(DIM / 128, NSLOT / 128, NEXP), 256, SMEM_BYTES>>>(b2);
    k_combine<<<N_TOK, 256>>>(out);
}

// round 4
// speedup vs baseline: 1.6504x; 1.6504x over previous
#include <cuda_runtime.h>
#include <cuda_fp16.h>
#include <stdint.h>
#include <math.h>

#define N_TOK 4096
#define DIM   1024
#define HID   4096
#define NEXP  8
#define NSLOT 8192
#define SLOT_PAD (NSLOT + 128)

// ---------------- scratch (__device__ globals only) ----------------
__device__ int g_counts[NEXP];
__device__ int g_cursor[NEXP];
__device__ int g_offsets[NEXP + 1];
__device__ int g_tg_e[N_TOK * 2];
__device__ float g_tg_w[N_TOK * 2];
__device__ int g_slot_token[NSLOT];
__device__ int g_tok_slot[N_TOK * 2];

__device__ __align__(16) __half g_Xg_hi[(size_t)SLOT_PAD * DIM];
__device__ __align__(16) __half g_Xg_lo[(size_t)SLOT_PAD * DIM];
__device__ __align__(16) __half g_Hg_hi[(size_t)SLOT_PAD * HID];
__device__ __align__(16) __half g_Hg_lo[(size_t)SLOT_PAD * HID];
__device__ __align__(16) __half g_W1t[(size_t)NEXP * HID * DIM]; // [e][h][d]
__device__ __align__(16) __half g_W2t[(size_t)NEXP * DIM * HID]; // [e][d][h]
__device__ __align__(16) float g_y[(size_t)SLOT_PAD * DIM];

// ---------------- helpers ----------------
__device__ __forceinline__ uint32_t smem_u32(const void* p) {
    uint32_t a;
    asm("{ .reg .u64 t; cvta.to.shared.u64 t, %1; cvt.u32.u64 %0, t; }" : "=r"(a) : "l"(p));
    return a;
}
__device__ __forceinline__ uint32_t pack2h(__half a, __half b) {
    return (uint32_t)__half_as_ushort(a) | ((uint32_t)__half_as_ushort(b) << 16);
}
__device__ __forceinline__ void cp16(uint32_t dst, const void* src) {
    asm volatile("cp.async.cg.shared.global [%0], [%1], 16;" :: "r"(dst), "l"(src));
}
#define CP_COMMIT() asm volatile("cp.async.commit_group;" ::: "memory")
#define CP_WAIT1()  asm volatile("cp.async.wait_group 1;" ::: "memory")

__device__ __forceinline__ void ldm4(uint32_t* r, uint32_t addr) {
    asm volatile("ldmatrix.sync.aligned.m8n8.x4.shared.b16 {%0,%1,%2,%3}, [%4];"
                 : "=r"(r[0]), "=r"(r[1]), "=r"(r[2]), "=r"(r[3]) : "r"(addr));
}
__device__ __forceinline__ void mma16816(float* c, const uint32_t* a, const uint32_t* b) {
    asm volatile("mma.sync.aligned.m16n8k16.row.col.f32.f16.f16.f32 "
                 "{%0,%1,%2,%3}, {%4,%5,%6,%7}, {%8,%9}, {%0,%1,%2,%3};"
                 : "+f"(c[0]), "+f"(c[1]), "+f"(c[2]), "+f"(c[3])
                 : "r"(a[0]), "r"(a[1]), "r"(a[2]), "r"(a[3]), "r"(b[0]), "r"(b[1]));
}

// ---------------- 1) gating ----------------
__global__ void k_reset() { if (threadIdx.x < NEXP) g_counts[threadIdx.x] = 0; }

__global__ void k_gate(const float* __restrict__ x, const float* __restrict__ Wg,
                       const float* __restrict__ bg) {
    int wid = threadIdx.x >> 5, lane = threadIdx.x & 31;
    int n = blockIdx.x * 8 + wid;
    float acc[8] = {0,0,0,0,0,0,0,0};
    const float4* wg4 = (const float4*)Wg;
    for (int k = lane; k < DIM; k += 32) {
        float xv = x[(size_t)n * DIM + k];
        float4 w0 = wg4[k * 2], w1 = wg4[k * 2 + 1];
        acc[0] = fmaf(xv, w0.x, acc[0]); acc[1] = fmaf(xv, w0.y, acc[1]);
        acc[2] = fmaf(xv, w0.z, acc[2]); acc[3] = fmaf(xv, w0.w, acc[3]);
        acc[4] = fmaf(xv, w1.x, acc[4]); acc[5] = fmaf(xv, w1.y, acc[5]);
        acc[6] = fmaf(xv, w1.z, acc[6]); acc[7] = fmaf(xv, w1.w, acc[7]);
    }
    #pragma unroll
    for (int e = 0; e < 8; e++)
        #pragma unroll
        for (int off = 16; off; off >>= 1)
            acc[e] += __shfl_down_sync(0xffffffffu, acc[e], off);
    if (lane == 0) {
        float s[8];
        #pragma unroll
        for (int e = 0; e < 8; e++) s[e] = acc[e] + bg[e];
        int e0 = 0; float s0 = s[0];
        #pragma unroll
        for (int e = 1; e < 8; e++) if (s[e] > s0) { s0 = s[e]; e0 = e; }
        int e1 = -1; float s1 = -3.0e38f;
        #pragma unroll
        for (int e = 0; e < 8; e++) if (e != e0 && s[e] > s1) { s1 = s[e]; e1 = e; }
        float t = expf(s1 - s0);
        g_tg_e[n * 2] = e0; g_tg_e[n * 2 + 1] = e1;
        g_tg_w[n * 2] = 1.f / (1.f + t); g_tg_w[n * 2 + 1] = t / (1.f + t);
        atomicAdd(&g_counts[e0], 1);
        atomicAdd(&g_counts[e1], 1);
    }
}

__global__ void k_scan() {
    int o = 0;
    for (int e = 0; e < NEXP; e++) { g_offsets[e] = o; o += g_counts[e]; g_cursor[e] = 0; }
    g_offsets[NEXP] = o;
}

__global__ void k_scatter() {
    int n = blockIdx.x * blockDim.x + threadIdx.x;
    if (n < N_TOK) {
        #pragma unroll
        for (int i = 0; i < 2; i++) {
            int e = g_tg_e[n * 2 + i];
            int slot = g_offsets[e] + atomicAdd(&g_cursor[e], 1);
            g_slot_token[slot] = n;
            g_tok_slot[n * 2 + i] = slot;
        }
    }
}

// ---------------- 2) gather x, fp16 hi/lo split ----------------
__global__ void k_gather(const float* __restrict__ x) {
    int s = blockIdx.x, t = threadIdx.x;
    int n = g_slot_token[s];
    const float4* xr = (const float4*)(x + (size_t)n * DIM);
    float4 a = xr[t * 2], b = xr[t * 2 + 1];
    float v[8] = {a.x, a.y, a.z, a.w, b.x, b.y, b.z, b.w};
    uint32_t ph[4], pl[4];
    #pragma unroll
    for (int i = 0; i < 4; i++) {
        __half h0 = __float2half_rn(v[2*i]), h1 = __float2half_rn(v[2*i+1]);
        ph[i] = pack2h(h0, h1);
        pl[i] = pack2h(__float2half_rn(v[2*i]   - __half2float(h0)),
                       __float2half_rn(v[2*i+1] - __half2float(h1)));
    }
    *(uint4*)(g_Xg_hi + (size_t)s * DIM + t * 8) = *(uint4*)ph;
    *(uint4*)(g_Xg_lo + (size_t)s * DIM + t * 8) = *(uint4*)pl;
}

// ---------------- 3) weight transpose to fp16: in[e][R][C] -> out[e][C][R] ----------------
__global__ void k_prep_w(const float* __restrict__ in, int R, int C, int which) {
    __half* o = which ? g_W2t : g_W1t;
    __shared__ float tile[32][33];
    int e = blockIdx.z;
    int r0 = blockIdx.y * 32, c0 = blockIdx.x * 32;
    int tx = threadIdx.x, ty = threadIdx.y;
    const float* ip = in + (size_t)e * R * C;
    #pragma unroll
    for (int j = 0; j < 32; j += 8)
        tile[ty + j][tx] = ip[(size_t)(r0 + ty + j) * C + c0 + tx];
    __syncthreads();
    size_t ob = (size_t)e * R * C;
    #pragma unroll
    for (int j = 0; j < 32; j += 8)
        o[ob + (size_t)(c0 + ty + j) * R + r0 + tx] = __float2half_rn(tile[tx][ty + j]);
}

// ---------------- 4) grouped GEMM (mma.sync fp16, A-split x2): 128x128x32 ----------------
// smem per stage: Ah | Al | B, each 128 rows * 80B (64B data + 16B pad)
#define ROWB   80
#define T_AH   0
#define T_AL   10240
#define T_B    20480
#define STAGEB 30720
#define NSTAGE 3
#define SMEM_BYTES (STAGEB * NSTAGE)

template <int KDIM, bool FFN1>
__global__ void __launch_bounds__(256) k_gemm(const float* __restrict__ bias_all) {
    constexpr int NTOT = FFN1 ? HID : DIM;
    constexpr int NCHUNK = KDIM / 32;
    extern __shared__ char sm[];
    uint32_t smb = smem_u32(sm);

    int e = blockIdx.z;
    int off_e = g_offsets[e];
    int cnt = g_offsets[e + 1] - off_e;
    int bm = blockIdx.y;
    if (bm * 128 >= cnt) return;
    int n_base = blockIdx.x * 128;
    int slot0 = off_e + bm * 128;

    int t = threadIdx.x;
    int warp = t >> 5, lane = t & 31;
    int wm = (warp & 3) * 32;      // warp M offset
    int wn = (warp >> 2) * 64;     // warp N offset

    const __half* Ah = (FFN1 ? g_Xg_hi : g_Hg_hi) + (size_t)slot0 * KDIM;
    const __half* Al = (FFN1 ? g_Xg_lo : g_Hg_lo) + (size_t)slot0 * KDIM;
    const __half* B  = (FFN1 ? g_W1t : g_W2t) + ((size_t)e * NTOT + n_base) * KDIM;
    const float* bias = bias_all + (size_t)e * NTOT;

    auto load_stage = [&](int stage, int ch) {
        uint32_t sb = smb + stage * STAGEB;
        int k0 = ch * 32;
        #pragma unroll
        for (int rep = 0; rep < 2; rep++) {
            int i = t + rep * 256;                 // 0..511
            int row = i >> 2, c = i & 3;
            uint32_t d = (uint32_t)(row * ROWB + c * 16);
            size_t src = (size_t)row * KDIM + k0 + c * 8;
            cp16(sb + T_AH + d, Ah + src);
            cp16(sb + T_AL + d, Al + src);
            cp16(sb + T_B  + d, B  + src);
        }
    };

    load_stage(0, 0); CP_COMMIT();
    load_stage(1, 1); CP_COMMIT();

    float acc[2][8][4];
    #pragma unroll
    for (int mt = 0; mt < 2; mt++)
        #pragma unroll
        for (int nt = 0; nt < 8; nt++)
            #pragma unroll
            for (int i = 0; i < 4; i++) acc[mt][nt][i] = 0.f;

    int g = lane >> 3, r8 = lane & 7;
    uint32_t aRow = (uint32_t)(wm + r8 + (g & 1) * 8);
    uint32_t aK   = (uint32_t)((g >> 1) * 8);
    uint32_t bRow = (uint32_t)(wn + r8 + (g >> 1) * 8);
    uint32_t bK   = (uint32_t)((g & 1) * 8);

    for (int ch = 0; ch < NCHUNK; ch++) {
        CP_WAIT1();
        __syncthreads();
        if (ch + 2 < NCHUNK) load_stage((ch + 2) % NSTAGE, ch + 2);
        CP_COMMIT();

        uint32_t sb = smb + (ch % NSTAGE) * STAGEB;
        #pragma unroll
        for (int kc = 0; kc < 2; kc++) {
            uint32_t a_hi[2][4], a_lo[2][4];
            #pragma unroll
            for (int mt = 0; mt < 2; mt++) {
                uint32_t ad = sb + (aRow + mt * 16) * ROWB + (kc * 16 + aK) * 2;
                ldm4(a_hi[mt], ad + T_AH);
                ldm4(a_lo[mt], ad + T_AL);
            }
            uint32_t bf[4][4];
            #pragma unroll
            for (int np = 0; np < 4; np++) {
                uint32_t bd = sb + (bRow + np * 16) * ROWB + (kc * 16 + bK) * 2;
                ldm4(bf[np], bd + T_B);
            }
            #pragma unroll
            for (int mt = 0; mt < 2; mt++)
                #pragma unroll
                for (int nt = 0; nt < 8; nt++) {
                    const uint32_t* bb = &bf[nt >> 1][(nt & 1) * 2];
                    mma16816(acc[mt][nt], a_hi[mt], bb);
                    mma16816(acc[mt][nt], a_lo[mt], bb);
                }
        }
        __syncthreads();
    }

    // epilogue
    int rlo = lane >> 2;            // 0..7
    int cpair = (lane & 3) * 2;     // 0,2,4,6
    #pragma unroll
    for (int mt = 0; mt < 2; mt++) {
        #pragma unroll
        for (int half = 0; half < 2; half++) {
            int m = bm * 128 + wm + mt * 16 + half * 8 + rlo;
            if (m >= cnt) continue;
            int slot = off_e + m;
            #pragma unroll
            for (int nt = 0; nt < 8; nt++) {
                int col = n_base + wn + nt * 8 + cpair;
                float v0 = acc[mt][nt][half * 2]     + bias[col];
                float v1 = acc[mt][nt][half * 2 + 1] + bias[col + 1];
                if (FFN1) {
                    v0 = fmaxf(v0, 0.f); v1 = fmaxf(v1, 0.f);
                    __half h0 = __float2half_rn(v0), h1 = __float2half_rn(v1);
                    size_t o = (size_t)slot * HID + col;
                    *(uint32_t*)(g_Hg_hi + o) = pack2h(h0, h1);
                    *(uint32_t*)(g_Hg_lo + o) =
                        pack2h(__float2half_rn(v0 - __half2float(h0)),
                               __float2half_rn(v1 - __half2float(h1)));
                } else {
                    size_t o = (size_t)slot * DIM + col;
                    float2 f2; f2.x = v0; f2.y = v1;
                    *(float2*)(g_y + o) = f2;
                }
            }
        }
    }
}

// ---------------- 5) combine ----------------
__global__ void k_combine(float* __restrict__ out) {
    int n = blockIdx.x, t = threadIdx.x;
    int s0 = g_tok_slot[n * 2], s1 = g_tok_slot[n * 2 + 1];
    float w0 = g_tg_w[n * 2], w1 = g_tg_w[n * 2 + 1];
    float4 a = ((const float4*)(g_y + (size_t)s0 * DIM))[t];
    float4 b = ((const float4*)(g_y + (size_t)s1 * DIM))[t];
    float4 o;
    o.x = w0 * a.x + w1 * b.x; o.y = w0 * a.y + w1 * b.y;
    o.z = w0 * a.z + w1 * b.z; o.w = w0 * a.w + w1 * b.w;
    ((float4*)(out + (size_t)n * DIM))[t] = o;
}

// ---------------- launch ----------------
extern "C" void kernel_launch(void* const* d_in, const int* in_sizes, int n_in,
                              void* d_out, int out_size) {
    const float* x  = (const float*)d_in[0];
    const float* Wg = (const float*)d_in[1];
    const float* bg = (const float*)d_in[2];
    const float* W1 = (const float*)d_in[3];
    const float* b1 = (const float*)d_in[4];
    const float* W2 = (const float*)d_in[5];
    const float* b2 = (const float*)d_in[6];
    float* out = (float*)d_out;

    cudaFuncSetAttribute(k_gemm<DIM, true>,  cudaFuncAttributeMaxDynamicSharedMemorySize, SMEM_BYTES);
    cudaFuncSetAttribute(k_gemm<HID, false>, cudaFuncAttributeMaxDynamicSharedMemorySize, SMEM_BYTES);

    k_reset<<<1, 32>>>();
    k_gate<<<N_TOK / 8, 256>>>(x, Wg, bg);
    k_scan<<<1, 1>>>();
    k_scatter<<<N_TOK / 256, 256>>>();
    k_gather<<<NSLOT, 128>>>(x);
    k_prep_w<<<dim3(HID / 32, DIM / 32, NEXP), dim3(32, 8)>>>(W1, DIM, HID, 0);
    k_prep_w<<<dim3(DIM / 32, HID / 32, NEXP), dim3(32, 8)>>>(W2, HID, DIM, 1);
    k_gemm<DIM, true><<<dim3(HID / 128, NSLOT / 128, NEXP), 256, SMEM_BYTES>>>(b1);
    k_gemm<HID, false><<<dim3(DIM / 128, NSLOT / 128, NEXP), 256, SMEM_BYTES>>>(b2);
    k_combine<<<N_TOK, 256>>>(out);
}

// round 5
// speedup vs baseline: 2.5287x; 1.5322x over previous
#include <cuda_runtime.h>
#include <cuda_fp16.h>
#include <stdint.h>
#include <math.h>

#define N_TOK 4096
#define DIM   1024
#define HID   4096
#define NEXP  8
#define NSLOT 8192
#define SLOT_PAD (NSLOT + 128)

// ---------------- scratch (__device__ globals only) ----------------
__device__ int g_counts[NEXP];
__device__ int g_cursor[NEXP];
__device__ int g_offsets[NEXP + 1];
__device__ int g_tg_e[N_TOK * 2];
__device__ float g_tg_w[N_TOK * 2];
__device__ int g_slot_token[NSLOT];
__device__ int g_tok_slot[N_TOK * 2];

__device__ __align__(16) __half g_Xg[(size_t)SLOT_PAD * DIM];
__device__ __align__(16) __half g_Hg[(size_t)SLOT_PAD * HID];
__device__ __align__(16) __half g_W1t[(size_t)NEXP * HID * DIM]; // [e][h][d]
__device__ __align__(16) __half g_W2t[(size_t)NEXP * DIM * HID]; // [e][d][h]
__device__ __align__(16) float g_y[(size_t)SLOT_PAD * DIM];

// ---------------- helpers ----------------
__device__ __forceinline__ uint32_t smem_u32(const void* p) {
    uint32_t a;
    asm("{ .reg .u64 t; cvta.to.shared.u64 t, %1; cvt.u32.u64 %0, t; }" : "=r"(a) : "l"(p));
    return a;
}
__device__ __forceinline__ uint32_t pack2h(__half a, __half b) {
    return (uint32_t)__half_as_ushort(a) | ((uint32_t)__half_as_ushort(b) << 16);
}
__device__ __forceinline__ void cp16(uint32_t dst, const void* src) {
    asm volatile("cp.async.cg.shared.global [%0], [%1], 16;" :: "r"(dst), "l"(src));
}
#define CP_COMMIT() asm volatile("cp.async.commit_group;" ::: "memory")
#define CP_WAIT2()  asm volatile("cp.async.wait_group 2;" ::: "memory")

__device__ __forceinline__ void ldm4(uint32_t* r, uint32_t addr) {
    asm volatile("ldmatrix.sync.aligned.m8n8.x4.shared.b16 {%0,%1,%2,%3}, [%4];"
                 : "=r"(r[0]), "=r"(r[1]), "=r"(r[2]), "=r"(r[3]) : "r"(addr));
}
__device__ __forceinline__ void mma16816(float* c, const uint32_t* a, const uint32_t* b) {
    asm volatile("mma.sync.aligned.m16n8k16.row.col.f32.f16.f16.f32 "
                 "{%0,%1,%2,%3}, {%4,%5,%6,%7}, {%8,%9}, {%0,%1,%2,%3};"
                 : "+f"(c[0]), "+f"(c[1]), "+f"(c[2]), "+f"(c[3])
                 : "r"(a[0]), "r"(a[1]), "r"(a[2]), "r"(a[3]), "r"(b[0]), "r"(b[1]));
}

// ---------------- 1) gating ----------------
__global__ void k_reset() { if (threadIdx.x < NEXP) g_counts[threadIdx.x] = 0; }

__global__ void k_gate(const float* __restrict__ x, const float* __restrict__ Wg,
                       const float* __restrict__ bg) {
    int wid = threadIdx.x >> 5, lane = threadIdx.x & 31;
    int n = blockIdx.x * 8 + wid;
    float acc[8] = {0,0,0,0,0,0,0,0};
    const float4* wg4 = (const float4*)Wg;
    for (int k = lane; k < DIM; k += 32) {
        float xv = x[(size_t)n * DIM + k];
        float4 w0 = wg4[k * 2], w1 = wg4[k * 2 + 1];
        acc[0] = fmaf(xv, w0.x, acc[0]); acc[1] = fmaf(xv, w0.y, acc[1]);
        acc[2] = fmaf(xv, w0.z, acc[2]); acc[3] = fmaf(xv, w0.w, acc[3]);
        acc[4] = fmaf(xv, w1.x, acc[4]); acc[5] = fmaf(xv, w1.y, acc[5]);
        acc[6] = fmaf(xv, w1.z, acc[6]); acc[7] = fmaf(xv, w1.w, acc[7]);
    }
    #pragma unroll
    for (int e = 0; e < 8; e++)
        #pragma unroll
        for (int off = 16; off; off >>= 1)
            acc[e] += __shfl_down_sync(0xffffffffu, acc[e], off);
    if (lane == 0) {
        float s[8];
        #pragma unroll
        for (int e = 0; e < 8; e++) s[e] = acc[e] + bg[e];
        int e0 = 0; float s0 = s[0];
        #pragma unroll
        for (int e = 1; e < 8; e++) if (s[e] > s0) { s0 = s[e]; e0 = e; }
        int e1 = -1; float s1 = -3.0e38f;
        #pragma unroll
        for (int e = 0; e < 8; e++) if (e != e0 && s[e] > s1) { s1 = s[e]; e1 = e; }
        float t = expf(s1 - s0);
        g_tg_e[n * 2] = e0; g_tg_e[n * 2 + 1] = e1;
        g_tg_w[n * 2] = 1.f / (1.f + t); g_tg_w[n * 2 + 1] = t / (1.f + t);
        atomicAdd(&g_counts[e0], 1);
        atomicAdd(&g_counts[e1], 1);
    }
}

__global__ void k_scan() {
    int o = 0;
    for (int e = 0; e < NEXP; e++) { g_offsets[e] = o; o += g_counts[e]; g_cursor[e] = 0; }
    g_offsets[NEXP] = o;
}

__global__ void k_scatter() {
    int n = blockIdx.x * blockDim.x + threadIdx.x;
    if (n < N_TOK) {
        #pragma unroll
        for (int i = 0; i < 2; i++) {
            int e = g_tg_e[n * 2 + i];
            int slot = g_offsets[e] + atomicAdd(&g_cursor[e], 1);
            g_slot_token[slot] = n;
            g_tok_slot[n * 2 + i] = slot;
        }
    }
}

// ---------------- 2) gather x -> fp16 ----------------
__global__ void k_gather(const float* __restrict__ x) {
    int s = blockIdx.x, t = threadIdx.x;
    int n = g_slot_token[s];
    const float4* xr = (const float4*)(x + (size_t)n * DIM);
    float4 a = xr[t * 2], b = xr[t * 2 + 1];
    uint32_t p[4];
    p[0] = pack2h(__float2half_rn(a.x), __float2half_rn(a.y));
    p[1] = pack2h(__float2half_rn(a.z), __float2half_rn(a.w));
    p[2] = pack2h(__float2half_rn(b.x), __float2half_rn(b.y));
    p[3] = pack2h(__float2half_rn(b.z), __float2half_rn(b.w));
    *(uint4*)(g_Xg + (size_t)s * DIM + t * 8) = *(uint4*)p;
}

// ---------------- 3) weight transpose to fp16: in[e][R][C] -> out[e][C][R] ----------------
__global__ void k_prep_w(const float* __restrict__ in, int R, int C, int which) {
    __half* o = which ? g_W2t : g_W1t;
    __shared__ float tile[32][33];
    int e = blockIdx.z;
    int r0 = blockIdx.y * 32, c0 = blockIdx.x * 32;
    int tx = threadIdx.x, ty = threadIdx.y;
    const float* ip = in + (size_t)e * R * C;
    #pragma unroll
    for (int j = 0; j < 32; j += 8)
        tile[ty + j][tx] = ip[(size_t)(r0 + ty + j) * C + c0 + tx];
    __syncthreads();
    size_t ob = (size_t)e * R * C;
    #pragma unroll
    for (int j = 0; j < 32; j += 8)
        o[ob + (size_t)(c0 + ty + j) * R + r0 + tx] = __float2half_rn(tile[tx][ty + j]);
}

// ---------------- 4) grouped GEMM (mma.sync fp16 single-pass): 128x128x32, 4-stage ----------------
// smem per stage: A | B, each 128 rows * 80B (64B data + 16B pad)
#define ROWB   80
#define T_A    0
#define T_B    10240
#define STAGEB 20480
#define NSTAGE 4
#define SMEM_BYTES (STAGEB * NSTAGE)

template <int KDIM, bool FFN1>
__global__ void __launch_bounds__(256) k_gemm(const float* __restrict__ bias_all) {
    constexpr int NTOT = FFN1 ? HID : DIM;
    constexpr int NCHUNK = KDIM / 32;
    extern __shared__ char sm[];
    uint32_t smb = smem_u32(sm);

    int e = blockIdx.z;
    int off_e = g_offsets[e];
    int cnt = g_offsets[e + 1] - off_e;
    int bm = blockIdx.y;
    if (bm * 128 >= cnt) return;
    int n_base = blockIdx.x * 128;
    int slot0 = off_e + bm * 128;

    int t = threadIdx.x;
    int warp = t >> 5, lane = t & 31;
    int wm = (warp & 3) * 32;      // warp M offset
    int wn = (warp >> 2) * 64;     // warp N offset

    const __half* A = (FFN1 ? g_Xg : g_Hg) + (size_t)slot0 * KDIM;
    const __half* B = (FFN1 ? g_W1t : g_W2t) + ((size_t)e * NTOT + n_base) * KDIM;
    const float* bias = bias_all + (size_t)e * NTOT;

    auto load_stage = [&](int stage, int ch) {
        uint32_t sb = smb + stage * STAGEB;
        int k0 = ch * 32;
        #pragma unroll
        for (int rep = 0; rep < 2; rep++) {
            int i = t + rep * 256;                 // 0..511
            int row = i >> 2, c = i & 3;
            uint32_t d = (uint32_t)(row * ROWB + c * 16);
            size_t src = (size_t)row * KDIM + k0 + c * 8;
            cp16(sb + T_A + d, A + src);
            cp16(sb + T_B + d, B + src);
        }
    };

    load_stage(0, 0); CP_COMMIT();
    load_stage(1, 1); CP_COMMIT();
    load_stage(2, 2); CP_COMMIT();

    float acc[2][8][4];
    #pragma unroll
    for (int mt = 0; mt < 2; mt++)
        #pragma unroll
        for (int nt = 0; nt < 8; nt++)
            #pragma unroll
            for (int i = 0; i < 4; i++) acc[mt][nt][i] = 0.f;

    int g = lane >> 3, r8 = lane & 7;
    uint32_t aRow = (uint32_t)(wm + r8 + (g & 1) * 8);
    uint32_t aK   = (uint32_t)((g >> 1) * 8);
    uint32_t bRow = (uint32_t)(wn + r8 + (g >> 1) * 8);
    uint32_t bK   = (uint32_t)((g & 1) * 8);

    for (int ch = 0; ch < NCHUNK; ch++) {
        CP_WAIT2();
        __syncthreads();
        if (ch + 3 < NCHUNK) load_stage((ch + 3) % NSTAGE, ch + 3);
        CP_COMMIT();

        uint32_t sb = smb + (ch % NSTAGE) * STAGEB;
        #pragma unroll
        for (int kc = 0; kc < 2; kc++) {
            uint32_t af[2][4];
            #pragma unroll
            for (int mt = 0; mt < 2; mt++) {
                uint32_t ad = sb + (aRow + mt * 16) * ROWB + (kc * 16 + aK) * 2;
                ldm4(af[mt], ad + T_A);
            }
            uint32_t bf[4][4];
            #pragma unroll
            for (int np = 0; np < 4; np++) {
                uint32_t bd = sb + (bRow + np * 16) * ROWB + (kc * 16 + bK) * 2;
                ldm4(bf[np], bd + T_B);
            }
            #pragma unroll
            for (int mt = 0; mt < 2; mt++)
                #pragma unroll
                for (int nt = 0; nt < 8; nt++)
                    mma16816(acc[mt][nt], af[mt], &bf[nt >> 1][(nt & 1) * 2]);
        }
        __syncthreads();
    }

    // epilogue
    int rlo = lane >> 2;            // 0..7
    int cpair = (lane & 3) * 2;     // 0,2,4,6
    #pragma unroll
    for (int mt = 0; mt < 2; mt++) {
        #pragma unroll
        for (int half = 0; half < 2; half++) {
            int m = bm * 128 + wm + mt * 16 + half * 8 + rlo;
            if (m >= cnt) continue;
            int slot = off_e + m;
            #pragma unroll
            for (int nt = 0; nt < 8; nt++) {
                int col = n_base + wn + nt * 8 + cpair;
                float v0 = acc[mt][nt][half * 2]     + bias[col];
                float v1 = acc[mt][nt][half * 2 + 1] + bias[col + 1];
                if (FFN1) {
                    v0 = fmaxf(v0, 0.f); v1 = fmaxf(v1, 0.f);
                    size_t o = (size_t)slot * HID + col;
                    *(uint32_t*)(g_Hg + o) =
                        pack2h(__float2half_rn(v0), __float2half_rn(v1));
                } else {
                    size_t o = (size_t)slot * DIM + col;
                    float2 f2; f2.x = v0; f2.y = v1;
                    *(float2*)(g_y + o) = f2;
                }
            }
        }
    }
}

// ---------------- 5) combine ----------------
__global__ void k_combine(float* __restrict__ out) {
    int n = blockIdx.x, t = threadIdx.x;
    int s0 = g_tok_slot[n * 2], s1 = g_tok_slot[n * 2 + 1];
    float w0 = g_tg_w[n * 2], w1 = g_tg_w[n * 2 + 1];
    float4 a = ((const float4*)(g_y + (size_t)s0 * DIM))[t];
    float4 b = ((const float4*)(g_y + (size_t)s1 * DIM))[t];
    float4 o;
    o.x = w0 * a.x + w1 * b.x; o.y = w0 * a.y + w1 * b.y;
    o.z = w0 * a.z + w1 * b.z; o.w = w0 * a.w + w1 * b.w;
    ((float4*)(out + (size_t)n * DIM))[t] = o;
}

// ---------------- launch ----------------
extern "C" void kernel_launch(void* const* d_in, const int* in_sizes, int n_in,
                              void* d_out, int out_size) {
    const float* x  = (const float*)d_in[0];
    const float* Wg = (const float*)d_in[1];
    const float* bg = (const float*)d_in[2];
    const float* W1 = (const float*)d_in[3];
    const float* b1 = (const float*)d_in[4];
    const float* W2 = (const float*)d_in[5];
    const float* b2 = (const float*)d_in[6];
    float* out = (float*)d_out;

    cudaFuncSetAttribute(k_gemm<DIM, true>,  cudaFuncAttributeMaxDynamicSharedMemorySize, SMEM_BYTES);
    cudaFuncSetAttribute(k_gemm<HID, false>, cudaFuncAttributeMaxDynamicSharedMemorySize, SMEM_BYTES);

    k_reset<<<1, 32>>>();
    k_gate<<<N_TOK / 8, 256>>>(x, Wg, bg);
    k_scan<<<1, 1>>>();
    k_scatter<<<N_TOK / 256, 256>>>();
    k_gather<<<NSLOT, 128>>>(x);
    k_prep_w<<<dim3(HID / 32, DIM / 32, NEXP), dim3(32, 8)>>>(W1, DIM, HID, 0);
    k_prep_w<<<dim3(DIM / 32, HID / 32, NEXP), dim3(32, 8)>>>(W2, HID, DIM, 1);
    k_gemm<DIM, true><<<dim3(HID / 128, NSLOT / 128, NEXP), 256, SMEM_BYTES>>>(b1);
    k_gemm<HID, false><<<dim3(DIM / 128, NSLOT / 128, NEXP), 256, SMEM_BYTES>>>(b2);
    k_combine<<<N_TOK, 256>>>(out);
}

// round 6
// speedup vs baseline: 2.6286x; 1.0395x over previous
#include <cuda_runtime.h>
#include <cuda_fp16.h>
#include <stdint.h>
#include <math.h>

#define N_TOK 4096
#define DIM   1024
#define HID   4096
#define NEXP  8
#define NSLOT 8192
#define SLOT_PAD (NSLOT + 128)
#define MAX_TILES 72

// ---------------- scratch (__device__ globals only) ----------------
__device__ int g_counts[NEXP];
__device__ int g_cursor[NEXP];
__device__ int g_offsets[NEXP + 1];
__device__ int g_tg_e[N_TOK * 2];
__device__ float g_tg_w[N_TOK * 2];
__device__ int g_slot_token[NSLOT];
__device__ int g_tok_slot[N_TOK * 2];
__device__ int g_tile_e[MAX_TILES];
__device__ int g_tile_bm[MAX_TILES];
__device__ int g_ntiles;

__device__ __align__(16) __half g_Xg[(size_t)SLOT_PAD * DIM];
__device__ __align__(16) __half g_Hg[(size_t)SLOT_PAD * HID];
__device__ __align__(16) __half g_W1t[(size_t)NEXP * HID * DIM]; // [e][h][d]
__device__ __align__(16) __half g_W2t[(size_t)NEXP * DIM * HID]; // [e][d][h]
__device__ __align__(16) float g_y[(size_t)SLOT_PAD * DIM];

// ---------------- helpers ----------------
__device__ __forceinline__ uint32_t smem_u32(const void* p) {
    uint32_t a;
    asm("{ .reg .u64 t; cvta.to.shared.u64 t, %1; cvt.u32.u64 %0, t; }" : "=r"(a) : "l"(p));
    return a;
}
__device__ __forceinline__ uint32_t pack2h(__half a, __half b) {
    return (uint32_t)__half_as_ushort(a) | ((uint32_t)__half_as_ushort(b) << 16);
}
__device__ __forceinline__ void cp16(uint32_t dst, const void* src) {
    asm volatile("cp.async.cg.shared.global [%0], [%1], 16;" :: "r"(dst), "l"(src));
}
#define CP_COMMIT() asm volatile("cp.async.commit_group;" ::: "memory")
#define CP_WAIT2()  asm volatile("cp.async.wait_group 2;" ::: "memory")

__device__ __forceinline__ void ldm4(uint32_t* r, uint32_t addr) {
    asm volatile("ldmatrix.sync.aligned.m8n8.x4.shared.b16 {%0,%1,%2,%3}, [%4];"
                 : "=r"(r[0]), "=r"(r[1]), "=r"(r[2]), "=r"(r[3]) : "r"(addr));
}
__device__ __forceinline__ void mma16816(float* c, const uint32_t* a, const uint32_t* b) {
    asm volatile("mma.sync.aligned.m16n8k16.row.col.f32.f16.f16.f32 "
                 "{%0,%1,%2,%3}, {%4,%5,%6,%7}, {%8,%9}, {%0,%1,%2,%3};"
                 : "+f"(c[0]), "+f"(c[1]), "+f"(c[2]), "+f"(c[3])
                 : "r"(a[0]), "r"(a[1]), "r"(a[2]), "r"(a[3]), "r"(b[0]), "r"(b[1]));
}

// ---------------- 1) gating ----------------
__global__ void k_reset() { if (threadIdx.x < NEXP) g_counts[threadIdx.x] = 0; }

__global__ void k_gate(const float* __restrict__ x, const float* __restrict__ Wg,
                       const float* __restrict__ bg) {
    int wid = threadIdx.x >> 5, lane = threadIdx.x & 31;
    int n = blockIdx.x * 8 + wid;
    float acc[8] = {0,0,0,0,0,0,0,0};
    const float4* wg4 = (const float4*)Wg;
    for (int k = lane; k < DIM; k += 32) {
        float xv = x[(size_t)n * DIM + k];
        float4 w0 = wg4[k * 2], w1 = wg4[k * 2 + 1];
        acc[0] = fmaf(xv, w0.x, acc[0]); acc[1] = fmaf(xv, w0.y, acc[1]);
        acc[2] = fmaf(xv, w0.z, acc[2]); acc[3] = fmaf(xv, w0.w, acc[3]);
        acc[4] = fmaf(xv, w1.x, acc[4]); acc[5] = fmaf(xv, w1.y, acc[5]);
        acc[6] = fmaf(xv, w1.z, acc[6]); acc[7] = fmaf(xv, w1.w, acc[7]);
    }
    #pragma unroll
    for (int e = 0; e < 8; e++)
        #pragma unroll
        for (int off = 16; off; off >>= 1)
            acc[e] += __shfl_down_sync(0xffffffffu, acc[e], off);
    if (lane == 0) {
        float s[8];
        #pragma unroll
        for (int e = 0; e < 8; e++) s[e] = acc[e] + bg[e];
        int e0 = 0; float s0 = s[0];
        #pragma unroll
        for (int e = 1; e < 8; e++) if (s[e] > s0) { s0 = s[e]; e0 = e; }
        int e1 = -1; float s1 = -3.0e38f;
        #pragma unroll
        for (int e = 0; e < 8; e++) if (e != e0 && s[e] > s1) { s1 = s[e]; e1 = e; }
        float t = expf(s1 - s0);
        g_tg_e[n * 2] = e0; g_tg_e[n * 2 + 1] = e1;
        g_tg_w[n * 2] = 1.f / (1.f + t); g_tg_w[n * 2 + 1] = t / (1.f + t);
        atomicAdd(&g_counts[e0], 1);
        atomicAdd(&g_counts[e1], 1);
    }
}

__global__ void k_scan() {
    int o = 0, tt = 0;
    for (int e = 0; e < NEXP; e++) {
        g_offsets[e] = o;
        int c = g_counts[e];
        for (int bm = 0; bm * 128 < c; bm++) { g_tile_e[tt] = e; g_tile_bm[tt] = bm; tt++; }
        o += c; g_cursor[e] = 0;
    }
    g_offsets[NEXP] = o;
    g_ntiles = tt;
}

__global__ void k_scatter() {
    int n = blockIdx.x * blockDim.x + threadIdx.x;
    if (n < N_TOK) {
        #pragma unroll
        for (int i = 0; i < 2; i++) {
            int e = g_tg_e[n * 2 + i];
            int slot = g_offsets[e] + atomicAdd(&g_cursor[e], 1);
            g_slot_token[slot] = n;
            g_tok_slot[n * 2 + i] = slot;
        }
    }
}

// ---------------- 2) gather x -> fp16 ----------------
__global__ void k_gather(const float* __restrict__ x) {
    int s = blockIdx.x, t = threadIdx.x;
    int n = g_slot_token[s];
    const float4* xr = (const float4*)(x + (size_t)n * DIM);
    float4 a = xr[t * 2], b = xr[t * 2 + 1];
    uint32_t p[4];
    p[0] = pack2h(__float2half_rn(a.x), __float2half_rn(a.y));
    p[1] = pack2h(__float2half_rn(a.z), __float2half_rn(a.w));
    p[2] = pack2h(__float2half_rn(b.x), __float2half_rn(b.y));
    p[3] = pack2h(__float2half_rn(b.z), __float2half_rn(b.w));
    *(uint4*)(g_Xg + (size_t)s * DIM + t * 8) = *(uint4*)p;
}

// ---------------- 3) weight transpose to fp16: in[e][R][C] -> out[e][C][R] ----------------
// 64(R) x 32(C) input tile, packed half2 coalesced stores.
__global__ void k_prep_w(const float* __restrict__ in, int R, int C, int which) {
    __half* o = which ? g_W2t : g_W1t;
    __shared__ float tile[32][65];   // [c][r]
    int e = blockIdx.z;
    int r0 = blockIdx.y * 64, c0 = blockIdx.x * 32;
    int tx = threadIdx.x, ty = threadIdx.y;   // 32 x 8
    const float* ip = in + (size_t)e * R * C;
    #pragma unroll
    for (int j = 0; j < 64; j += 8)
        tile[tx][ty + j] = ip[(size_t)(r0 + ty + j) * C + c0 + tx];
    __syncthreads();
    size_t ob = (size_t)e * R * C;
    int t = ty * 32 + tx;
    #pragma unroll
    for (int i = t; i < 1024; i += 256) {
        int c = i >> 5;            // 0..31
        int rp = (i & 31) * 2;     // 0..62
        uint32_t v = pack2h(__float2half_rn(tile[c][rp]),
                            __float2half_rn(tile[c][rp + 1]));
        *(uint32_t*)(o + ob + (size_t)(c0 + c) * R + r0 + rp) = v;
    }
}

// ---------------- 4) grouped GEMM (mma.sync fp16): 128x128x32, 4-stage, 1 sync/chunk ----------------
#define ROWB   80
#define T_A    0
#define T_B    10240
#define STAGEB 20480
#define NSTAGE 4
#define SMEM_BYTES (STAGEB * NSTAGE)

template <int KDIM, bool FFN1>
__global__ void __launch_bounds__(256) k_gemm(const float* __restrict__ bias_all) {
    constexpr int NTOT = FFN1 ? HID : DIM;
    constexpr int NCHUNK = KDIM / 32;
    extern __shared__ char sm[];
    uint32_t smb = smem_u32(sm);

    int tile = blockIdx.y;
    if (tile >= g_ntiles) return;
    int e = g_tile_e[tile];
    int bm = g_tile_bm[tile];
    int off_e = g_offsets[e];
    int cnt = g_offsets[e + 1] - off_e;
    int n_base = blockIdx.x * 128;
    int slot0 = off_e + bm * 128;

    int t = threadIdx.x;
    int warp = t >> 5, lane = t & 31;
    int wm = (warp & 3) * 32;      // warp M offset
    int wn = (warp >> 2) * 64;     // warp N offset

    const __half* A = (FFN1 ? g_Xg : g_Hg) + (size_t)slot0 * KDIM;
    const __half* B = (FFN1 ? g_W1t : g_W2t) + ((size_t)e * NTOT + n_base) * KDIM;
    const float* bias = bias_all + (size_t)e * NTOT;

    auto load_stage = [&](int stage, int ch) {
        uint32_t sb = smb + stage * STAGEB;
        int k0 = ch * 32;
        #pragma unroll
        for (int rep = 0; rep < 2; rep++) {
            int i = t + rep * 256;                 // 0..511
            int row = i >> 2, c = i & 3;
            uint32_t d = (uint32_t)(row * ROWB + c * 16);
            size_t src = (size_t)row * KDIM + k0 + c * 8;
            cp16(sb + T_A + d, A + src);
            cp16(sb + T_B + d, B + src);
        }
    };

    load_stage(0, 0); CP_COMMIT();
    load_stage(1, 1); CP_COMMIT();
    load_stage(2, 2); CP_COMMIT();

    float acc[2][8][4];
    #pragma unroll
    for (int mt = 0; mt < 2; mt++)
        #pragma unroll
        for (int nt = 0; nt < 8; nt++)
            #pragma unroll
            for (int i = 0; i < 4; i++) acc[mt][nt][i] = 0.f;

    int g = lane >> 3, r8 = lane & 7;
    uint32_t aRow = (uint32_t)(wm + r8 + (g & 1) * 8);
    uint32_t aK   = (uint32_t)((g >> 1) * 8);
    uint32_t bRow = (uint32_t)(wn + r8 + (g >> 1) * 8);
    uint32_t bK   = (uint32_t)((g & 1) * 8);

    for (int ch = 0; ch < NCHUNK; ch++) {
        CP_WAIT2();
        __syncthreads();      // single barrier: orders compute(ch-1) before overwrite of its stage
        if (ch + 3 < NCHUNK) load_stage((ch + 3) % NSTAGE, ch + 3);
        CP_COMMIT();

        uint32_t sb = smb + (ch % NSTAGE) * STAGEB;
        #pragma unroll
        for (int kc = 0; kc < 2; kc++) {
            uint32_t af[2][4];
            #pragma unroll
            for (int mt = 0; mt < 2; mt++) {
                uint32_t ad = sb + (aRow + mt * 16) * ROWB + (kc * 16 + aK) * 2;
                ldm4(af[mt], ad + T_A);
            }
            uint32_t bf[4][4];
            #pragma unroll
            for (int np = 0; np < 4; np++) {
                uint32_t bd = sb + (bRow + np * 16) * ROWB + (kc * 16 + bK) * 2;
                ldm4(bf[np], bd + T_B);
            }
            #pragma unroll
            for (int mt = 0; mt < 2; mt++)
                #pragma unroll
                for (int nt = 0; nt < 8; nt++)
                    mma16816(acc[mt][nt], af[mt], &bf[nt >> 1][(nt & 1) * 2]);
        }
    }

    // epilogue
    int rlo = lane >> 2;            // 0..7
    int cpair = (lane & 3) * 2;     // 0,2,4,6
    #pragma unroll
    for (int mt = 0; mt < 2; mt++) {
        #pragma unroll
        for (int half = 0; half < 2; half++) {
            int m = bm * 128 + wm + mt * 16 + half * 8 + rlo;
            if (m >= cnt) continue;
            int slot = off_e + m;
            #pragma unroll
            for (int nt = 0; nt < 8; nt++) {
                int col = n_base + wn + nt * 8 + cpair;
                float v0 = acc[mt][nt][half * 2]     + bias[col];
                float v1 = acc[mt][nt][half * 2 + 1] + bias[col + 1];
                if (FFN1) {
                    v0 = fmaxf(v0, 0.f); v1 = fmaxf(v1, 0.f);
                    size_t o = (size_t)slot * HID + col;
                    *(uint32_t*)(g_Hg + o) =
                        pack2h(__float2half_rn(v0), __float2half_rn(v1));
                } else {
                    size_t o = (size_t)slot * DIM + col;
                    float2 f2; f2.x = v0; f2.y = v1;
                    *(float2*)(g_y + o) = f2;
                }
            }
        }
    }
}

// ---------------- 5) combine ----------------
__global__ void k_combine(float* __restrict__ out) {
    int n = blockIdx.x, t = threadIdx.x;
    int s0 = g_tok_slot[n * 2], s1 = g_tok_slot[n * 2 + 1];
    float w0 = g_tg_w[n * 2], w1 = g_tg_w[n * 2 + 1];
    float4 a = ((const float4*)(g_y + (size_t)s0 * DIM))[t];
    float4 b = ((const float4*)(g_y + (size_t)s1 * DIM))[t];
    float4 o;
    o.x = w0 * a.x + w1 * b.x; o.y = w0 * a.y + w1 * b.y;
    o.z = w0 * a.z + w1 * b.z; o.w = w0 * a.w + w1 * b.w;
    ((float4*)(out + (size_t)n * DIM))[t] = o;
}

// ---------------- launch ----------------
extern "C" void kernel_launch(void* const* d_in, const int* in_sizes, int n_in,
                              void* d_out, int out_size) {
    const float* x  = (const float*)d_in[0];
    const float* Wg = (const float*)d_in[1];
    const float* bg = (const float*)d_in[2];
    const float* W1 = (const float*)d_in[3];
    const float* b1 = (const float*)d_in[4];
    const float* W2 = (const float*)d_in[5];
    const float* b2 = (const float*)d_in[6];
    float* out = (float*)d_out;

    cudaFuncSetAttribute(k_gemm<DIM, true>,  cudaFuncAttributeMaxDynamicSharedMemorySize, SMEM_BYTES);
    cudaFuncSetAttribute(k_gemm<HID, false>, cudaFuncAttributeMaxDynamicSharedMemorySize, SMEM_BYTES);

    k_reset<<<1, 32>>>();
    k_gate<<<N_TOK / 8, 256>>>(x, Wg, bg);
    k_scan<<<1, 1>>>();
    k_scatter<<<N_TOK / 256, 256>>>();
    k_gather<<<NSLOT, 128>>>(x);
    k_prep_w<<<dim3(HID / 32, DIM / 64, NEXP), dim3(32, 8)>>>(W1, DIM, HID, 0);
    k_prep_w<<<dim3(DIM / 32, HID / 64, NEXP), dim3(32, 8)>>>(W2, HID, DIM, 1);
    k_gemm<DIM, true><<<dim3(HID / 128, MAX_TILES), 256, SMEM_BYTES>>>(b1);
    k_gemm<HID, false><<<dim3(DIM / 128, MAX_TILES), 256, SMEM_BYTES>>>(b2);
    k_combine<<<N_TOK, 256>>>(out);
}

// round 7
// speedup vs baseline: 2.6566x; 1.0107x over previous
#include <cuda_runtime.h>
#include <cuda_fp16.h>
#include <stdint.h>
#include <math.h>

#define N_TOK 4096
#define DIM   1024
#define HID   4096
#define NEXP  8
#define NSLOT 8192
#define SLOT_PAD (NSLOT + 128)
#define MAX_TILES 72

// ---------------- scratch (__device__ globals only) ----------------
__device__ int g_offsets[NEXP + 1];
__device__ int g_tg_e[N_TOK * 2];
__device__ float g_tg_w[N_TOK * 2];
__device__ int g_slot_token[NSLOT];
__device__ int g_tok_slot[N_TOK * 2];
__device__ int g_tile_e[MAX_TILES];
__device__ int g_tile_bm[MAX_TILES];
__device__ int g_ntiles;

__device__ __align__(16) __half g_Xg[(size_t)SLOT_PAD * DIM];
__device__ __align__(16) __half g_Hg[(size_t)SLOT_PAD * HID];
__device__ __align__(16) __half g_W1t[(size_t)NEXP * HID * DIM]; // [e][h][d]
__device__ __align__(16) __half g_W2t[(size_t)NEXP * DIM * HID]; // [e][d][h]
__device__ __align__(16) float g_y[(size_t)SLOT_PAD * DIM];

// ---------------- helpers ----------------
__device__ __forceinline__ uint32_t smem_u32(const void* p) {
    uint32_t a;
    asm("{ .reg .u64 t; cvta.to.shared.u64 t, %1; cvt.u32.u64 %0, t; }" : "=r"(a) : "l"(p));
    return a;
}
__device__ __forceinline__ uint32_t pack2h(__half a, __half b) {
    return (uint32_t)__half_as_ushort(a) | ((uint32_t)__half_as_ushort(b) << 16);
}
__device__ __forceinline__ void cp16(uint32_t dst, const void* src) {
    asm volatile("cp.async.cg.shared.global [%0], [%1], 16;" :: "r"(dst), "l"(src));
}
#define CP_COMMIT() asm volatile("cp.async.commit_group;" ::: "memory")
#define CP_WAIT2()  asm volatile("cp.async.wait_group 2;" ::: "memory")

__device__ __forceinline__ void ldm4(uint32_t* r, uint32_t addr) {
    asm volatile("ldmatrix.sync.aligned.m8n8.x4.shared.b16 {%0,%1,%2,%3}, [%4];"
                 : "=r"(r[0]), "=r"(r[1]), "=r"(r[2]), "=r"(r[3]) : "r"(addr));
}
__device__ __forceinline__ void mma16816(float* c, const uint32_t* a, const uint32_t* b) {
    asm volatile("mma.sync.aligned.m16n8k16.row.col.f32.f16.f16.f32 "
                 "{%0,%1,%2,%3}, {%4,%5,%6,%7}, {%8,%9}, {%0,%1,%2,%3};"
                 : "+f"(c[0]), "+f"(c[1]), "+f"(c[2]), "+f"(c[3])
                 : "r"(a[0]), "r"(a[1]), "r"(a[2]), "r"(a[3]), "r"(b[0]), "r"(b[1]));
}

// ---------------- 1) gating ----------------
__global__ void k_gate(const float* __restrict__ x, const float* __restrict__ Wg,
                       const float* __restrict__ bg) {
    int wid = threadIdx.x >> 5, lane = threadIdx.x & 31;
    int n = blockIdx.x * 8 + wid;
    float acc[8] = {0,0,0,0,0,0,0,0};
    const float4* wg4 = (const float4*)Wg;
    for (int k = lane; k < DIM; k += 32) {
        float xv = x[(size_t)n * DIM + k];
        float4 w0 = wg4[k * 2], w1 = wg4[k * 2 + 1];
        acc[0] = fmaf(xv, w0.x, acc[0]); acc[1] = fmaf(xv, w0.y, acc[1]);
        acc[2] = fmaf(xv, w0.z, acc[2]); acc[3] = fmaf(xv, w0.w, acc[3]);
        acc[4] = fmaf(xv, w1.x, acc[4]); acc[5] = fmaf(xv, w1.y, acc[5]);
        acc[6] = fmaf(xv, w1.z, acc[6]); acc[7] = fmaf(xv, w1.w, acc[7]);
    }
    #pragma unroll
    for (int e = 0; e < 8; e++)
        #pragma unroll
        for (int off = 16; off; off >>= 1)
            acc[e] += __shfl_down_sync(0xffffffffu, acc[e], off);
    if (lane == 0) {
        float s[8];
        #pragma unroll
        for (int e = 0; e < 8; e++) s[e] = acc[e] + bg[e];
        int e0 = 0; float s0 = s[0];
        #pragma unroll
        for (int e = 1; e < 8; e++) if (s[e] > s0) { s0 = s[e]; e0 = e; }
        int e1 = -1; float s1 = -3.0e38f;
        #pragma unroll
        for (int e = 0; e < 8; e++) if (e != e0 && s[e] > s1) { s1 = s[e]; e1 = e; }
        float t = expf(s1 - s0);
        g_tg_e[n * 2] = e0; g_tg_e[n * 2 + 1] = e1;
        g_tg_w[n * 2] = 1.f / (1.f + t); g_tg_w[n * 2 + 1] = t / (1.f + t);
    }
}

// ---------------- 1b) fused scan + tile map + scatter (single block) ----------------
__global__ void k_scanscatter() {
    __shared__ int cnt[NEXP], off[NEXP], cur[NEXP];
    int t = threadIdx.x;
    if (t < NEXP) cnt[t] = 0;
    __syncthreads();
    for (int i = t; i < N_TOK * 2; i += 256) atomicAdd(&cnt[g_tg_e[i]], 1);
    __syncthreads();
    if (t == 0) {
        int o = 0, tt = 0;
        for (int e = 0; e < NEXP; e++) {
            off[e] = o; g_offsets[e] = o; cur[e] = 0;
            int c = cnt[e];
            for (int bm = 0; bm * 128 < c; bm++) { g_tile_e[tt] = e; g_tile_bm[tt] = bm; tt++; }
            o += c;
        }
        g_offsets[NEXP] = o;
        g_ntiles = tt;
    }
    __syncthreads();
    for (int i = t; i < N_TOK * 2; i += 256) {
        int e = g_tg_e[i];
        int slot = off[e] + atomicAdd(&cur[e], 1);
        g_slot_token[slot] = i >> 1;
        g_tok_slot[i] = slot;
    }
}

// ---------------- 2) gather x -> fp16 ----------------
__global__ void k_gather(const float* __restrict__ x) {
    int s = blockIdx.x, t = threadIdx.x;
    int n = g_slot_token[s];
    const float4* xr = (const float4*)(x + (size_t)n * DIM);
    float4 a = xr[t * 2], b = xr[t * 2 + 1];
    uint32_t p[4];
    p[0] = pack2h(__float2half_rn(a.x), __float2half_rn(a.y));
    p[1] = pack2h(__float2half_rn(a.z), __float2half_rn(a.w));
    p[2] = pack2h(__float2half_rn(b.x), __float2half_rn(b.y));
    p[3] = pack2h(__float2half_rn(b.z), __float2half_rn(b.w));
    *(uint4*)(g_Xg + (size_t)s * DIM + t * 8) = *(uint4*)p;
}

// ---------------- 3) weight transpose to fp16: in[e][R][C] -> out[e][C][R] ----------------
__global__ void k_prep_w(const float* __restrict__ in, int R, int C, int which) {
    __half* o = which ? g_W2t : g_W1t;
    __shared__ float tile[32][65];   // [c][r]
    int e = blockIdx.z;
    int r0 = blockIdx.y * 64, c0 = blockIdx.x * 32;
    int tx = threadIdx.x, ty = threadIdx.y;   // 32 x 8
    const float* ip = in + (size_t)e * R * C;
    #pragma unroll
    for (int j = 0; j < 64; j += 8)
        tile[tx][ty + j] = ip[(size_t)(r0 + ty + j) * C + c0 + tx];
    __syncthreads();
    size_t ob = (size_t)e * R * C;
    int t = ty * 32 + tx;
    #pragma unroll
    for (int i = t; i < 1024; i += 256) {
        int c = i >> 5;            // 0..31
        int rp = (i & 31) * 2;     // 0..62
        uint32_t v = pack2h(__float2half_rn(tile[c][rp]),
                            __float2half_rn(tile[c][rp + 1]));
        *(uint32_t*)(o + ob + (size_t)(c0 + c) * R + r0 + rp) = v;
    }
}

// ---------------- 4) grouped GEMM (mma.sync fp16): 128x128x32, 4-stage, 1 sync/chunk ----------------
#define ROWB   80
#define T_A    0
#define T_B    10240
#define STAGEB 20480
#define NSTAGE 4
#define SMEM_BYTES (STAGEB * NSTAGE)

template <int KDIM, bool FFN1>
__global__ void __launch_bounds__(256) k_gemm(const float* __restrict__ bias_all) {
    constexpr int NTOT = FFN1 ? HID : DIM;
    constexpr int NCHUNK = KDIM / 32;
    extern __shared__ char sm[];
    uint32_t smb = smem_u32(sm);

    int tile = blockIdx.y;
    if (tile >= g_ntiles) return;
    int e = g_tile_e[tile];
    int bm = g_tile_bm[tile];
    int off_e = g_offsets[e];
    int cnt = g_offsets[e + 1] - off_e;
    int n_base = blockIdx.x * 128;
    int slot0 = off_e + bm * 128;

    int t = threadIdx.x;
    int warp = t >> 5, lane = t & 31;
    int wm = (warp & 3) * 32;      // warp M offset
    int wn = (warp >> 2) * 64;     // warp N offset

    const __half* A = (FFN1 ? g_Xg : g_Hg) + (size_t)slot0 * KDIM;
    const __half* B = (FFN1 ? g_W1t : g_W2t) + ((size_t)e * NTOT + n_base) * KDIM;
    const float* bias = bias_all + (size_t)e * NTOT;

    auto load_stage = [&](int stage, int ch) {
        uint32_t sb = smb + stage * STAGEB;
        int k0 = ch * 32;
        #pragma unroll
        for (int rep = 0; rep < 2; rep++) {
            int i = t + rep * 256;                 // 0..511
            int row = i >> 2, c = i & 3;
            uint32_t d = (uint32_t)(row * ROWB + c * 16);
            size_t src = (size_t)row * KDIM + k0 + c * 8;
            cp16(sb + T_A + d, A + src);
            cp16(sb + T_B + d, B + src);
        }
    };

    load_stage(0, 0); CP_COMMIT();
    load_stage(1, 1); CP_COMMIT();
    load_stage(2, 2); CP_COMMIT();

    float acc[2][8][4];
    #pragma unroll
    for (int mt = 0; mt < 2; mt++)
        #pragma unroll
        for (int nt = 0; nt < 8; nt++)
            #pragma unroll
            for (int i = 0; i < 4; i++) acc[mt][nt][i] = 0.f;

    int g = lane >> 3, r8 = lane & 7;
    uint32_t aRow = (uint32_t)(wm + r8 + (g & 1) * 8);
    uint32_t aK   = (uint32_t)((g >> 1) * 8);
    uint32_t bRow = (uint32_t)(wn + r8 + (g >> 1) * 8);
    uint32_t bK   = (uint32_t)((g & 1) * 8);

    for (int ch = 0; ch < NCHUNK; ch++) {
        CP_WAIT2();
        __syncthreads();      // single barrier: orders compute(ch-1) before overwrite of its stage
        if (ch + 3 < NCHUNK) load_stage((ch + 3) % NSTAGE, ch + 3);
        CP_COMMIT();

        uint32_t sb = smb + (ch % NSTAGE) * STAGEB;
        #pragma unroll
        for (int kc = 0; kc < 2; kc++) {
            uint32_t af[2][4];
            #pragma unroll
            for (int mt = 0; mt < 2; mt++) {
                uint32_t ad = sb + (aRow + mt * 16) * ROWB + (kc * 16 + aK) * 2;
                ldm4(af[mt], ad + T_A);
            }
            uint32_t bf[4][4];
            #pragma unroll
            for (int np = 0; np < 4; np++) {
                uint32_t bd = sb + (bRow + np * 16) * ROWB + (kc * 16 + bK) * 2;
                ldm4(bf[np], bd + T_B);
            }
            #pragma unroll
            for (int mt = 0; mt < 2; mt++)
                #pragma unroll
                for (int nt = 0; nt < 8; nt++)
                    mma16816(acc[mt][nt], af[mt], &bf[nt >> 1][(nt & 1) * 2]);
        }
    }

    // epilogue
    int rlo = lane >> 2;            // 0..7
    int cpair = (lane & 3) * 2;     // 0,2,4,6
    #pragma unroll
    for (int mt = 0; mt < 2; mt++) {
        #pragma unroll
        for (int half = 0; half < 2; half++) {
            int m = bm * 128 + wm + mt * 16 + half * 8 + rlo;
            if (m >= cnt) continue;
            int slot = off_e + m;
            #pragma unroll
            for (int nt = 0; nt < 8; nt++) {
                int col = n_base + wn + nt * 8 + cpair;
                float v0 = acc[mt][nt][half * 2]     + bias[col];
                float v1 = acc[mt][nt][half * 2 + 1] + bias[col + 1];
                if (FFN1) {
                    v0 = fmaxf(v0, 0.f); v1 = fmaxf(v1, 0.f);
                    size_t o = (size_t)slot * HID + col;
                    *(uint32_t*)(g_Hg + o) =
                        pack2h(__float2half_rn(v0), __float2half_rn(v1));
                } else {
                    size_t o = (size_t)slot * DIM + col;
                    float2 f2; f2.x = v0; f2.y = v1;
                    *(float2*)(g_y + o) = f2;
                }
            }
        }
    }
}

// ---------------- 5) combine ----------------
__global__ void k_combine(float* __restrict__ out) {
    int n = blockIdx.x, t = threadIdx.x;
    int s0 = g_tok_slot[n * 2], s1 = g_tok_slot[n * 2 + 1];
    float w0 = g_tg_w[n * 2], w1 = g_tg_w[n * 2 + 1];
    float4 a = ((const float4*)(g_y + (size_t)s0 * DIM))[t];
    float4 b = ((const float4*)(g_y + (size_t)s1 * DIM))[t];
    float4 o;
    o.x = w0 * a.x + w1 * b.x; o.y = w0 * a.y + w1 * b.y;
    o.z = w0 * a.z + w1 * b.z; o.w = w0 * a.w + w1 * b.w;
    ((float4*)(out + (size_t)n * DIM))[t] = o;
}

// ---------------- launch (fork/join: weight prep overlaps routing + GEMM1) ----------------
extern "C" void kernel_launch(void* const* d_in, const int* in_sizes, int n_in,
                              void* d_out, int out_size) {
    const float* x  = (const float*)d_in[0];
    const float* Wg = (const float*)d_in[1];
    const float* bg = (const float*)d_in[2];
    const float* W1 = (const float*)d_in[3];
    const float* b1 = (const float*)d_in[4];
    const float* W2 = (const float*)d_in[5];
    const float* b2 = (const float*)d_in[6];
    float* out = (float*)d_out;

    static cudaStream_t s2 = []() {
        cudaStream_t s; cudaStreamCreateWithFlags(&s, cudaStreamNonBlocking); return s;
    }();
    static cudaEvent_t evF = []() {
        cudaEvent_t e; cudaEventCreateWithFlags(&e, cudaEventDisableTiming); return e;
    }();
    static cudaEvent_t ev1 = []() {
        cudaEvent_t e; cudaEventCreateWithFlags(&e, cudaEventDisableTiming); return e;
    }();
    static cudaEvent_t ev2 = []() {
        cudaEvent_t e; cudaEventCreateWithFlags(&e, cudaEventDisableTiming); return e;
    }();

    cudaFuncSetAttribute(k_gemm<DIM, true>,  cudaFuncAttributeMaxDynamicSharedMemorySize, SMEM_BYTES);
    cudaFuncSetAttribute(k_gemm<HID, false>, cudaFuncAttributeMaxDynamicSharedMemorySize, SMEM_BYTES);

    // fork: weight prep on side stream (no routing deps)
    cudaEventRecord(evF, 0);
    cudaStreamWaitEvent(s2, evF, 0);
    k_prep_w<<<dim3(HID / 32, DIM / 64, NEXP), dim3(32, 8), 0, s2>>>(W1, DIM, HID, 0);
    cudaEventRecord(ev1, s2);
    k_prep_w<<<dim3(DIM / 32, HID / 64, NEXP), dim3(32, 8), 0, s2>>>(W2, HID, DIM, 1);
    cudaEventRecord(ev2, s2);

    // main branch: routing
    k_gate<<<N_TOK / 8, 256>>>(x, Wg, bg);
    k_scanscatter<<<1, 256>>>();
    k_gather<<<NSLOT, 128>>>(x);

    // join W1, then GEMM1
    cudaStreamWaitEvent(0, ev1, 0);
    k_gemm<DIM, true><<<dim3(HID / 128, MAX_TILES), 256, SMEM_BYTES>>>(b1);
    // join W2, then GEMM2
    cudaStreamWaitEvent(0, ev2, 0);
    k_gemm<HID, false><<<dim3(DIM / 128, MAX_TILES), 256, SMEM_BYTES>>>(b2);
    k_combine<<<N_TOK, 256>>>(out);
}

// round 8
// speedup vs baseline: 2.8099x; 1.0577x over previous
#include <cuda_runtime.h>
#include <cuda_fp16.h>
#include <stdint.h>
#include <math.h>

#define N_TOK 4096
#define DIM   1024
#define HID   4096
#define NEXP  8
#define NSLOT 8192
#define SLOT_PAD (NSLOT + 128)
#define MAX_TILES 72

// ---------------- scratch (__device__ globals only) ----------------
__device__ int g_offsets[NEXP + 1];
__device__ int g_tg_e[N_TOK * 2];
__device__ float g_tg_w[N_TOK * 2];
__device__ int g_slot_token[NSLOT];
__device__ int g_tok_slot[N_TOK * 2];
__device__ int g_tile_e[MAX_TILES];
__device__ int g_tile_bm[MAX_TILES];
__device__ int g_ntiles;

__device__ __align__(16) __half g_Xg[(size_t)SLOT_PAD * DIM];
__device__ __align__(16) __half g_Hg[(size_t)SLOT_PAD * HID];
__device__ __align__(16) __half g_W1t[(size_t)NEXP * HID * DIM]; // [e][h][d]
__device__ __align__(16) __half g_W2t[(size_t)NEXP * DIM * HID]; // [e][d][h]
__device__ __align__(16) float g_y[(size_t)SLOT_PAD * DIM];

// ---------------- helpers ----------------
__device__ __forceinline__ uint32_t smem_u32(const void* p) {
    uint32_t a;
    asm("{ .reg .u64 t; cvta.to.shared.u64 t, %1; cvt.u32.u64 %0, t; }" : "=r"(a) : "l"(p));
    return a;
}
__device__ __forceinline__ uint32_t pack2h(__half a, __half b) {
    return (uint32_t)__half_as_ushort(a) | ((uint32_t)__half_as_ushort(b) << 16);
}
__device__ __forceinline__ void cp16(uint32_t dst, const void* src) {
    asm volatile("cp.async.cg.shared.global [%0], [%1], 16;" :: "r"(dst), "l"(src));
}
#define CP_COMMIT() asm volatile("cp.async.commit_group;" ::: "memory")
#define CP_WAIT2()  asm volatile("cp.async.wait_group 2;" ::: "memory")

__device__ __forceinline__ void ldm4(uint32_t* r, uint32_t addr) {
    asm volatile("ldmatrix.sync.aligned.m8n8.x4.shared.b16 {%0,%1,%2,%3}, [%4];"
                 : "=r"(r[0]), "=r"(r[1]), "=r"(r[2]), "=r"(r[3]) : "r"(addr));
}
__device__ __forceinline__ void mma16816(float* c, const uint32_t* a, const uint32_t* b) {
    asm volatile("mma.sync.aligned.m16n8k16.row.col.f32.f16.f16.f32 "
                 "{%0,%1,%2,%3}, {%4,%5,%6,%7}, {%8,%9}, {%0,%1,%2,%3};"
                 : "+f"(c[0]), "+f"(c[1]), "+f"(c[2]), "+f"(c[3])
                 : "r"(a[0]), "r"(a[1]), "r"(a[2]), "r"(a[3]), "r"(b[0]), "r"(b[1]));
}

// ---------------- 1) gating ----------------
__global__ void k_gate(const float* __restrict__ x, const float* __restrict__ Wg,
                       const float* __restrict__ bg) {
    int wid = threadIdx.x >> 5, lane = threadIdx.x & 31;
    int n = blockIdx.x * 8 + wid;
    float acc[8] = {0,0,0,0,0,0,0,0};
    const float4* wg4 = (const float4*)Wg;
    for (int k = lane; k < DIM; k += 32) {
        float xv = x[(size_t)n * DIM + k];
        float4 w0 = wg4[k * 2], w1 = wg4[k * 2 + 1];
        acc[0] = fmaf(xv, w0.x, acc[0]); acc[1] = fmaf(xv, w0.y, acc[1]);
        acc[2] = fmaf(xv, w0.z, acc[2]); acc[3] = fmaf(xv, w0.w, acc[3]);
        acc[4] = fmaf(xv, w1.x, acc[4]); acc[5] = fmaf(xv, w1.y, acc[5]);
        acc[6] = fmaf(xv, w1.z, acc[6]); acc[7] = fmaf(xv, w1.w, acc[7]);
    }
    #pragma unroll
    for (int e = 0; e < 8; e++)
        #pragma unroll
        for (int off = 16; off; off >>= 1)
            acc[e] += __shfl_down_sync(0xffffffffu, acc[e], off);
    if (lane == 0) {
        float s[8];
        #pragma unroll
        for (int e = 0; e < 8; e++) s[e] = acc[e] + bg[e];
        int e0 = 0; float s0 = s[0];
        #pragma unroll
        for (int e = 1; e < 8; e++) if (s[e] > s0) { s0 = s[e]; e0 = e; }
        int e1 = -1; float s1 = -3.0e38f;
        #pragma unroll
        for (int e = 0; e < 8; e++) if (e != e0 && s[e] > s1) { s1 = s[e]; e1 = e; }
        float t = expf(s1 - s0);
        g_tg_e[n * 2] = e0; g_tg_e[n * 2 + 1] = e1;
        g_tg_w[n * 2] = 1.f / (1.f + t); g_tg_w[n * 2 + 1] = t / (1.f + t);
    }
}

// ---------------- 1b) fused scan + tile map + scatter (single block) ----------------
__global__ void k_scanscatter() {
    __shared__ int cnt[NEXP], off[NEXP], cur[NEXP];
    int t = threadIdx.x;
    if (t < NEXP) cnt[t] = 0;
    __syncthreads();
    for (int i = t; i < N_TOK * 2; i += 256) atomicAdd(&cnt[g_tg_e[i]], 1);
    __syncthreads();
    if (t == 0) {
        int o = 0, tt = 0;
        for (int e = 0; e < NEXP; e++) {
            off[e] = o; g_offsets[e] = o; cur[e] = 0;
            int c = cnt[e];
            for (int bm = 0; bm * 128 < c; bm++) { g_tile_e[tt] = e; g_tile_bm[tt] = bm; tt++; }
            o += c;
        }
        g_offsets[NEXP] = o;
        g_ntiles = tt;
    }
    __syncthreads();
    for (int i = t; i < N_TOK * 2; i += 256) {
        int e = g_tg_e[i];
        int slot = off[e] + atomicAdd(&cur[e], 1);
        g_slot_token[slot] = i >> 1;
        g_tok_slot[i] = slot;
    }
}

// ---------------- 2) gather x -> fp16 ----------------
__global__ void k_gather(const float* __restrict__ x) {
    int s = blockIdx.x, t = threadIdx.x;
    int n = g_slot_token[s];
    const float4* xr = (const float4*)(x + (size_t)n * DIM);
    float4 a = xr[t * 2], b = xr[t * 2 + 1];
    uint32_t p[4];
    p[0] = pack2h(__float2half_rn(a.x), __float2half_rn(a.y));
    p[1] = pack2h(__float2half_rn(a.z), __float2half_rn(a.w));
    p[2] = pack2h(__float2half_rn(b.x), __float2half_rn(b.y));
    p[3] = pack2h(__float2half_rn(b.z), __float2half_rn(b.w));
    *(uint4*)(g_Xg + (size_t)s * DIM + t * 8) = *(uint4*)p;
}

// ---------------- 3) weight transpose to fp16: in[e][R][C] -> out[e][C][R] ----------------
__global__ void k_prep_w(const float* __restrict__ in, int R, int C, int which) {
    __half* o = which ? g_W2t : g_W1t;
    __shared__ float tile[32][65];   // [c][r]
    int e = blockIdx.z;
    int r0 = blockIdx.y * 64, c0 = blockIdx.x * 32;
    int tx = threadIdx.x, ty = threadIdx.y;   // 32 x 8
    const float* ip = in + (size_t)e * R * C;
    #pragma unroll
    for (int j = 0; j < 64; j += 8)
        tile[tx][ty + j] = ip[(size_t)(r0 + ty + j) * C + c0 + tx];
    __syncthreads();
    size_t ob = (size_t)e * R * C;
    int t = ty * 32 + tx;
    #pragma unroll
    for (int i = t; i < 1024; i += 256) {
        int c = i >> 5;            // 0..31
        int rp = (i & 31) * 2;     // 0..62
        uint32_t v = pack2h(__float2half_rn(tile[c][rp]),
                            __float2half_rn(tile[c][rp + 1]));
        *(uint32_t*)(o + ob + (size_t)(c0 + c) * R + r0 + rp) = v;
    }
}

// ---------------- 4) grouped GEMM: 128x128x32 CTA, 4 warps, warp tile 64x64 ----------------
#define ROWB   80
#define T_A    0
#define T_B    10240
#define STAGEB 20480
#define NSTAGE 4
#define SMEM_BYTES (STAGEB * NSTAGE)

template <int KDIM, bool FFN1>
__global__ void __launch_bounds__(128) k_gemm(const float* __restrict__ bias_all) {
    constexpr int NTOT = FFN1 ? HID : DIM;
    constexpr int NCHUNK = KDIM / 32;
    extern __shared__ char sm[];
    uint32_t smb = smem_u32(sm);

    int tile = blockIdx.y;
    if (tile >= g_ntiles) return;
    int e = g_tile_e[tile];
    int bm = g_tile_bm[tile];
    int off_e = g_offsets[e];
    int cnt = g_offsets[e + 1] - off_e;
    int n_base = blockIdx.x * 128;
    int slot0 = off_e + bm * 128;

    int t = threadIdx.x;
    int warp = t >> 5, lane = t & 31;
    int wm = (warp & 1) * 64;      // warp M offset
    int wn = (warp >> 1) * 64;     // warp N offset

    const __half* A = (FFN1 ? g_Xg : g_Hg) + (size_t)slot0 * KDIM;
    const __half* B = (FFN1 ? g_W1t : g_W2t) + ((size_t)e * NTOT + n_base) * KDIM;
    const float* bias = bias_all + (size_t)e * NTOT;

    auto load_stage = [&](int stage, int ch) {
        uint32_t sb = smb + stage * STAGEB;
        int k0 = ch * 32;
        #pragma unroll
        for (int rep = 0; rep < 4; rep++) {
            int i = t + rep * 128;                 // 0..511
            int row = i >> 2, c = i & 3;
            uint32_t d = (uint32_t)(row * ROWB + c * 16);
            size_t src = (size_t)row * KDIM + k0 + c * 8;
            cp16(sb + T_A + d, A + src);
            cp16(sb + T_B + d, B + src);
        }
    };

    load_stage(0, 0); CP_COMMIT();
    load_stage(1, 1); CP_COMMIT();
    load_stage(2, 2); CP_COMMIT();

    float acc[4][8][4];
    #pragma unroll
    for (int mt = 0; mt < 4; mt++)
        #pragma unroll
        for (int nt = 0; nt < 8; nt++)
            #pragma unroll
            for (int i = 0; i < 4; i++) acc[mt][nt][i] = 0.f;

    int g = lane >> 3, r8 = lane & 7;
    uint32_t aRow = (uint32_t)(wm + r8 + (g & 1) * 8);
    uint32_t aK   = (uint32_t)((g >> 1) * 8);
    uint32_t bRow = (uint32_t)(wn + r8 + (g >> 1) * 8);
    uint32_t bK   = (uint32_t)((g & 1) * 8);

    for (int ch = 0; ch < NCHUNK; ch++) {
        CP_WAIT2();
        __syncthreads();      // single barrier per chunk
        if (ch + 3 < NCHUNK) load_stage((ch + 3) % NSTAGE, ch + 3);
        CP_COMMIT();

        uint32_t sb = smb + (ch % NSTAGE) * STAGEB;
        #pragma unroll
        for (int kc = 0; kc < 2; kc++) {
            uint32_t af[4][4];
            #pragma unroll
            for (int mt = 0; mt < 4; mt++) {
                uint32_t ad = sb + (aRow + mt * 16) * ROWB + (kc * 16 + aK) * 2;
                ldm4(af[mt], ad + T_A);
            }
            uint32_t bf[4][4];
            #pragma unroll
            for (int np = 0; np < 4; np++) {
                uint32_t bd = sb + (bRow + np * 16) * ROWB + (kc * 16 + bK) * 2;
                ldm4(bf[np], bd + T_B);
            }
            #pragma unroll
            for (int mt = 0; mt < 4; mt++)
                #pragma unroll
                for (int nt = 0; nt < 8; nt++)
                    mma16816(acc[mt][nt], af[mt], &bf[nt >> 1][(nt & 1) * 2]);
        }
    }

    // epilogue
    int rlo = lane >> 2;            // 0..7
    int cpair = (lane & 3) * 2;     // 0,2,4,6
    #pragma unroll
    for (int mt = 0; mt < 4; mt++) {
        #pragma unroll
        for (int half = 0; half < 2; half++) {
            int m = bm * 128 + wm + mt * 16 + half * 8 + rlo;
            if (m >= cnt) continue;
            int slot = off_e + m;
            #pragma unroll
            for (int nt = 0; nt < 8; nt++) {
                int col = n_base + wn + nt * 8 + cpair;
                float v0 = acc[mt][nt][half * 2]     + bias[col];
                float v1 = acc[mt][nt][half * 2 + 1] + bias[col + 1];
                if (FFN1) {
                    v0 = fmaxf(v0, 0.f); v1 = fmaxf(v1, 0.f);
                    size_t o = (size_t)slot * HID + col;
                    *(uint32_t*)(g_Hg + o) =
                        pack2h(__float2half_rn(v0), __float2half_rn(v1));
                } else {
                    size_t o = (size_t)slot * DIM + col;
                    float2 f2; f2.x = v0; f2.y = v1;
                    *(float2*)(g_y + o) = f2;
                }
            }
        }
    }
}

// ---------------- 5) combine ----------------
__global__ void k_combine(float* __restrict__ out) {
    int n = blockIdx.x, t = threadIdx.x;
    int s0 = g_tok_slot[n * 2], s1 = g_tok_slot[n * 2 + 1];
    float w0 = g_tg_w[n * 2], w1 = g_tg_w[n * 2 + 1];
    float4 a = ((const float4*)(g_y + (size_t)s0 * DIM))[t];
    float4 b = ((const float4*)(g_y + (size_t)s1 * DIM))[t];
    float4 o;
    o.x = w0 * a.x + w1 * b.x; o.y = w0 * a.y + w1 * b.y;
    o.z = w0 * a.z + w1 * b.z; o.w = w0 * a.w + w1 * b.w;
    ((float4*)(out + (size_t)n * DIM))[t] = o;
}

// ---------------- launch (fork/join: weight prep overlaps routing + GEMM1) ----------------
extern "C" void kernel_launch(void* const* d_in, const int* in_sizes, int n_in,
                              void* d_out, int out_size) {
    const float* x  = (const float*)d_in[0];
    const float* Wg = (const float*)d_in[1];
    const float* bg = (const float*)d_in[2];
    const float* W1 = (const float*)d_in[3];
    const float* b1 = (const float*)d_in[4];
    const float* W2 = (const float*)d_in[5];
    const float* b2 = (const float*)d_in[6];
    float* out = (float*)d_out;

    static cudaStream_t s2 = []() {
        cudaStream_t s; cudaStreamCreateWithFlags(&s, cudaStreamNonBlocking); return s;
    }();
    static cudaEvent_t evF = []() {
        cudaEvent_t e; cudaEventCreateWithFlags(&e, cudaEventDisableTiming); return e;
    }();
    static cudaEvent_t ev1 = []() {
        cudaEvent_t e; cudaEventCreateWithFlags(&e, cudaEventDisableTiming); return e;
    }();
    static cudaEvent_t ev2 = []() {
        cudaEvent_t e; cudaEventCreateWithFlags(&e, cudaEventDisableTiming); return e;
    }();

    cudaFuncSetAttribute(k_gemm<DIM, true>,  cudaFuncAttributeMaxDynamicSharedMemorySize, SMEM_BYTES);
    cudaFuncSetAttribute(k_gemm<HID, false>, cudaFuncAttributeMaxDynamicSharedMemorySize, SMEM_BYTES);

    // fork: weight prep on side stream (no routing deps)
    cudaEventRecord(evF, 0);
    cudaStreamWaitEvent(s2, evF, 0);
    k_prep_w<<<dim3(HID / 32, DIM / 64, NEXP), dim3(32, 8), 0, s2>>>(W1, DIM, HID, 0);
    cudaEventRecord(ev1, s2);
    k_prep_w<<<dim3(DIM / 32, HID / 64, NEXP), dim3(32, 8), 0, s2>>>(W2, HID, DIM, 1);
    cudaEventRecord(ev2, s2);

    // main branch: routing
    k_gate<<<N_TOK / 8, 256>>>(x, Wg, bg);
    k_scanscatter<<<1, 256>>>();
    k_gather<<<NSLOT, 128>>>(x);

    // join W1, then GEMM1
    cudaStreamWaitEvent(0, ev1, 0);
    k_gemm<DIM, true><<<dim3(HID / 128, MAX_TILES), 128, SMEM_BYTES>>>(b1);
    // join W2, then GEMM2
    cudaStreamWaitEvent(0, ev2, 0);
    k_gemm<HID, false><<<dim3(DIM / 128, MAX_TILES), 128, SMEM_BYTES>>>(b2);
    k_combine<<<N_TOK, 256>>>(out);
}

// round 11
// speedup vs baseline: 2.8107x; 1.0003x over previous
#include <cuda_runtime.h>
#include <cuda_fp16.h>
#include <stdint.h>
#include <math.h>

#define N_TOK 4096
#define DIM   1024
#define HID   4096
#define NEXP  8
#define NSLOT 8192
#define SLOT_PAD (NSLOT + 128)
#define MAX_TILES 72

// ---------------- scratch (__device__ globals only) ----------------
__device__ int g_offsets[NEXP + 1];
__device__ int g_tg_e[N_TOK * 2];
__device__ float g_tg_w[N_TOK * 2];
__device__ int g_slot_token[NSLOT];
__device__ float g_slot_w[NSLOT];
__device__ int g_tile_e[MAX_TILES];
__device__ int g_tile_bm[MAX_TILES];
__device__ int g_ntiles;

__device__ __align__(16) __half g_Xg[(size_t)SLOT_PAD * DIM];
__device__ __align__(16) __half g_Hg[(size_t)SLOT_PAD * HID];
__device__ __align__(16) __half g_W1t[(size_t)NEXP * HID * DIM]; // [e][h][d]
__device__ __align__(16) __half g_W2t[(size_t)NEXP * DIM * HID]; // [e][d][h]

// ---------------- helpers ----------------
__device__ __forceinline__ uint32_t smem_u32(const void* p) {
    uint32_t a;
    asm("{ .reg .u64 t; cvta.to.shared.u64 t, %1; cvt.u32.u64 %0, t; }" : "=r"(a) : "l"(p));
    return a;
}
__device__ __forceinline__ uint32_t pack2h(__half a, __half b) {
    return (uint32_t)__half_as_ushort(a) | ((uint32_t)__half_as_ushort(b) << 16);
}
__device__ __forceinline__ void cp16(uint32_t dst, const void* src) {
    asm volatile("cp.async.cg.shared.global [%0], [%1], 16;" :: "r"(dst), "l"(src));
}
#define CP_COMMIT() asm volatile("cp.async.commit_group;" ::: "memory")
#define CP_WAIT2()  asm volatile("cp.async.wait_group 2;" ::: "memory")

__device__ __forceinline__ void ldm4(uint32_t* r, uint32_t addr) {
    asm volatile("ldmatrix.sync.aligned.m8n8.x4.shared.b16 {%0,%1,%2,%3}, [%4];"
                 : "=r"(r[0]), "=r"(r[1]), "=r"(r[2]), "=r"(r[3]) : "r"(addr));
}
__device__ __forceinline__ void mma16816(float* c, const uint32_t* a, const uint32_t* b) {
    asm volatile("mma.sync.aligned.m16n8k16.row.col.f32.f16.f16.f32 "
                 "{%0,%1,%2,%3}, {%4,%5,%6,%7}, {%8,%9}, {%0,%1,%2,%3};"
                 : "+f"(c[0]), "+f"(c[1]), "+f"(c[2]), "+f"(c[3])
                 : "r"(a[0]), "r"(a[1]), "r"(a[2]), "r"(a[3]), "r"(b[0]), "r"(b[1]));
}

// ---------------- 0) zero out ----------------
__global__ void k_zero_out(float* __restrict__ out) {
    int i = blockIdx.x * blockDim.x + threadIdx.x;
    ((float4*)out)[i] = make_float4(0.f, 0.f, 0.f, 0.f);
}

// ---------------- 1) gating ----------------
__global__ void k_gate(const float* __restrict__ x, const float* __restrict__ Wg,
                       const float* __restrict__ bg) {
    int wid = threadIdx.x >> 5, lane = threadIdx.x & 31;
    int n = blockIdx.x * 8 + wid;
    float acc[8] = {0,0,0,0,0,0,0,0};
    const float4* wg4 = (const float4*)Wg;
    for (int k = lane; k < DIM; k += 32) {
        float xv = x[(size_t)n * DIM + k];
        float4 w0 = wg4[k * 2], w1 = wg4[k * 2 + 1];
        acc[0] = fmaf(xv, w0.x, acc[0]); acc[1] = fmaf(xv, w0.y, acc[1]);
        acc[2] = fmaf(xv, w0.z, acc[2]); acc[3] = fmaf(xv, w0.w, acc[3]);
        acc[4] = fmaf(xv, w1.x, acc[4]); acc[5] = fmaf(xv, w1.y, acc[5]);
        acc[6] = fmaf(xv, w1.z, acc[6]); acc[7] = fmaf(xv, w1.w, acc[7]);
    }
    #pragma unroll
    for (int e = 0; e < 8; e++)
        #pragma unroll
        for (int off = 16; off; off >>= 1)
            acc[e] += __shfl_down_sync(0xffffffffu, acc[e], off);
    if (lane == 0) {
        float s[8];
        #pragma unroll
        for (int e = 0; e < 8; e++) s[e] = acc[e] + bg[e];
        int e0 = 0; float s0 = s[0];
        #pragma unroll
        for (int e = 1; e < 8; e++) if (s[e] > s0) { s0 = s[e]; e0 = e; }
        int e1 = -1; float s1 = -3.0e38f;
        #pragma unroll
        for (int e = 0; e < 8; e++) if (e != e0 && s[e] > s1) { s1 = s[e]; e1 = e; }
        float t = expf(s1 - s0);
        g_tg_e[n * 2] = e0; g_tg_e[n * 2 + 1] = e1;
        g_tg_w[n * 2] = 1.f / (1.f + t); g_tg_w[n * 2 + 1] = t / (1.f + t);
    }
}

// ---------------- 1b) fused scan + tile map + scatter (single block) ----------------
__global__ void k_scanscatter() {
    __shared__ int cnt[NEXP], off[NEXP], cur[NEXP];
    int t = threadIdx.x;
    if (t < NEXP) cnt[t] = 0;
    __syncthreads();
    for (int i = t; i < N_TOK * 2; i += 256) atomicAdd(&cnt[g_tg_e[i]], 1);
    __syncthreads();
    if (t == 0) {
        int o = 0, tt = 0;
        for (int e = 0; e < NEXP; e++) {
            off[e] = o; g_offsets[e] = o; cur[e] = 0;
            int c = cnt[e];
            for (int bm = 0; bm * 128 < c; bm++) { g_tile_e[tt] = e; g_tile_bm[tt] = bm; tt++; }
            o += c;
        }
        g_offsets[NEXP] = o;
        g_ntiles = tt;
    }
    __syncthreads();
    for (int i = t; i < N_TOK * 2; i += 256) {
        int e = g_tg_e[i];
        int slot = off[e] + atomicAdd(&cur[e], 1);
        g_slot_token[slot] = i >> 1;
        g_slot_w[slot] = g_tg_w[i];
    }
}

// ---------------- 2) gather x -> fp16 ----------------
__global__ void k_gather(const float* __restrict__ x) {
    int s = blockIdx.x, t = threadIdx.x;
    int n = g_slot_token[s];
    const float4* xr = (const float4*)(x + (size_t)n * DIM);
    float4 a = xr[t * 2], b = xr[t * 2 + 1];
    uint32_t p[4];
    p[0] = pack2h(__float2half_rn(a.x), __float2half_rn(a.y));
    p[1] = pack2h(__float2half_rn(a.z), __float2half_rn(a.w));
    p[2] = pack2h(__float2half_rn(b.x), __float2half_rn(b.y));
    p[3] = pack2h(__float2half_rn(b.z), __float2half_rn(b.w));
    *(uint4*)(g_Xg + (size_t)s * DIM + t * 8) = *(uint4*)p;
}

// ---------------- 3) weight transpose to fp16: in[e][R][C] -> out[e][C][R] ----------------
__global__ void k_prep_w(const float* __restrict__ in, int R, int C, int which) {
    __half* o = which ? g_W2t : g_W1t;
    __shared__ float tile[32][65];   // [c][r]
    int e = blockIdx.z;
    int r0 = blockIdx.y * 64, c0 = blockIdx.x * 32;
    int tx = threadIdx.x, ty = threadIdx.y;   // 32 x 8
    const float* ip = in + (size_t)e * R * C;
    #pragma unroll
    for (int j = 0; j < 64; j += 8)
        tile[tx][ty + j] = ip[(size_t)(r0 + ty + j) * C + c0 + tx];
    __syncthreads();
    size_t ob = (size_t)e * R * C;
    int t = ty * 32 + tx;
    #pragma unroll
    for (int i = t; i < 1024; i += 256) {
        int c = i >> 5;            // 0..31
        int rp = (i & 31) * 2;     // 0..62
        uint32_t v = pack2h(__float2half_rn(tile[c][rp]),
                            __float2half_rn(tile[c][rp + 1]));
        *(uint32_t*)(o + ob + (size_t)(c0 + c) * R + r0 + rp) = v;
    }
}

// ---------------- 4) grouped GEMM: 128x128x32 CTA, 4 warps 64x64, 4-stage ----------------
#define ROWB   80
#define T_A    0
#define T_B    10240
#define STAGEB 20480
#define NSTAGE 4
#define SMEM_BYTES (STAGEB * NSTAGE)

template <int KDIM, bool FFN1>
__global__ void __launch_bounds__(128) k_gemm(const float* __restrict__ bias_all,
                                              float* __restrict__ out) {
    constexpr int NTOT = FFN1 ? HID : DIM;
    constexpr int NCHUNK = KDIM / 32;
    extern __shared__ char sm[];
    uint32_t smb = smem_u32(sm);

    int tile = blockIdx.y;
    if (tile >= g_ntiles) return;
    int e = g_tile_e[tile];
    int bm = g_tile_bm[tile];
    int off_e = g_offsets[e];
    int cnt = g_offsets[e + 1] - off_e;
    int n_base = blockIdx.x * 128;
    int slot0 = off_e + bm * 128;

    int t = threadIdx.x;
    int warp = t >> 5, lane = t & 31;
    int wm = (warp & 1) * 64;      // warp M offset
    int wn = (warp >> 1) * 64;     // warp N offset

    const __half* A = (FFN1 ? g_Xg : g_Hg) + (size_t)slot0 * KDIM;
    const __half* B = (FFN1 ? g_W1t : g_W2t) + ((size_t)e * NTOT + n_base) * KDIM;
    const float* bias = bias_all + (size_t)e * NTOT;

    auto load_stage = [&](int stage, int ch) {
        uint32_t sb = smb + stage * STAGEB;
        int k0 = ch * 32;
        #pragma unroll
        for (int rep = 0; rep < 4; rep++) {
            int i = t + rep * 128;                 // 0..511
            int row = i >> 2, c = i & 3;
            uint32_t d = (uint32_t)(row * ROWB + c * 16);
            size_t src = (size_t)row * KDIM + k0 + c * 8;
            cp16(sb + T_A + d, A + src);
            cp16(sb + T_B + d, B + src);
        }
    };

    load_stage(0, 0); CP_COMMIT();
    load_stage(1, 1); CP_COMMIT();
    load_stage(2, 2); CP_COMMIT();

    float acc[4][8][4];
    #pragma unroll
    for (int mt = 0; mt < 4; mt++)
        #pragma unroll
        for (int nt = 0; nt < 8; nt++)
            #pragma unroll
            for (int i = 0; i < 4; i++) acc[mt][nt][i] = 0.f;

    int g = lane >> 3, r8 = lane & 7;
    uint32_t aRow = (uint32_t)(wm + r8 + (g & 1) * 8);
    uint32_t aK   = (uint32_t)((g >> 1) * 8);
    uint32_t bRow = (uint32_t)(wn + r8 + (g >> 1) * 8);
    uint32_t bK   = (uint32_t)((g & 1) * 8);

    for (int ch = 0; ch < NCHUNK; ch++) {
        CP_WAIT2();
        __syncthreads();      // single barrier per chunk
        if (ch + 3 < NCHUNK) load_stage((ch + 3) % NSTAGE, ch + 3);
        CP_COMMIT();

        uint32_t sb = smb + (ch % NSTAGE) * STAGEB;
        #pragma unroll
        for (int kc = 0; kc < 2; kc++) {
            uint32_t af[4][4];
            #pragma unroll
            for (int mt = 0; mt < 4; mt++) {
                uint32_t ad = sb + (aRow + mt * 16) * ROWB + (kc * 16 + aK) * 2;
                ldm4(af[mt], ad + T_A);
            }
            uint32_t bf[4][4];
            #pragma unroll
            for (int np = 0; np < 4; np++) {
                uint32_t bd = sb + (bRow + np * 16) * ROWB + (kc * 16 + bK) * 2;
                ldm4(bf[np], bd + T_B);
            }
            #pragma unroll
            for (int mt = 0; mt < 4; mt++)
                #pragma unroll
                for (int nt = 0; nt < 8; nt++)
                    mma16816(acc[mt][nt], af[mt], &bf[nt >> 1][(nt & 1) * 2]);
        }
    }

    // epilogue
    int rlo = lane >> 2;            // 0..7
    int cpair = (lane & 3) * 2;     // 0,2,4,6
    #pragma unroll
    for (int mt = 0; mt < 4; mt++) {
        #pragma unroll
        for (int half = 0; half < 2; half++) {
            int m = bm * 128 + wm + mt * 16 + half * 8 + rlo;
            if (m >= cnt) continue;
            int slot = off_e + m;
            if (FFN1) {
                #pragma unroll
                for (int nt = 0; nt < 8; nt++) {
                    int col = n_base + wn + nt * 8 + cpair;
                    float v0 = acc[mt][nt][half * 2]     + bias[col];
                    float v1 = acc[mt][nt][half * 2 + 1] + bias[col + 1];
                    v0 = fmaxf(v0, 0.f); v1 = fmaxf(v1, 0.f);
                    size_t o = (size_t)slot * HID + col;
                    *(uint32_t*)(g_Hg + o) =
                        pack2h(__float2half_rn(v0), __float2half_rn(v1));
                }
            } else {
                int token = g_slot_token[slot];
                float w = g_slot_w[slot];
                float* orow = out + (size_t)token * DIM;
                #pragma unroll
                for (int nt = 0; nt < 8; nt++) {
                    int col = n_base + wn + nt * 8 + cpair;
                    float v0 = acc[mt][nt][half * 2]     + bias[col];
                    float v1 = acc[mt][nt][half * 2 + 1] + bias[col + 1];
                    atomicAdd(orow + col,     w * v0);
                    atomicAdd(orow + col + 1, w * v1);
                }
            }
        }
    }
}

// ---------------- launch (fork/join: side stream does memset + weight prep) ----------------
extern "C" void kernel_launch(void* const* d_in, const int* in_sizes, int n_in,
                              void* d_out, int out_size) {
    const float* x  = (const float*)d_in[0];
    const float* Wg = (const float*)d_in[1];
    const float* bg = (const float*)d_in[2];
    const float* W1 = (const float*)d_in[3];
    const float* b1 = (const float*)d_in[4];
    const float* W2 = (const float*)d_in[5];
    const float* b2 = (const float*)d_in[6];
    float* out = (float*)d_out;

    static cudaStream_t s2 = []() {
        cudaStream_t s; cudaStreamCreateWithFlags(&s, cudaStreamNonBlocking); return s;
    }();
    static cudaEvent_t evF = []() {
        cudaEvent_t e; cudaEventCreateWithFlags(&e, cudaEventDisableTiming); return e;
    }();
    static cudaEvent_t ev1 = []() {
        cudaEvent_t e; cudaEventCreateWithFlags(&e, cudaEventDisableTiming); return e;
    }();
    static cudaEvent_t ev2 = []() {
        cudaEvent_t e; cudaEventCreateWithFlags(&e, cudaEventDisableTiming); return e;
    }();

    cudaFuncSetAttribute(k_gemm<DIM, true>,  cudaFuncAttributeMaxDynamicSharedMemorySize, SMEM_BYTES);
    cudaFuncSetAttribute(k_gemm<HID, false>, cudaFuncAttributeMaxDynamicSharedMemorySize, SMEM_BYTES);

    // fork: memset(out) + weight prep on side stream (no routing deps)
    cudaEventRecord(evF, 0);
    cudaStreamWaitEvent(s2, evF, 0);
    k_zero_out<<<(N_TOK * DIM / 4) / 256, 256, 0, s2>>>(out);
    k_prep_w<<<dim3(HID / 32, DIM / 64, NEXP), dim3(32, 8), 0, s2>>>(W1, DIM, HID, 0);
    cudaEventRecord(ev1, s2);
    k_prep_w<<<dim3(DIM / 32, HID / 64, NEXP), dim3(32, 8), 0, s2>>>(W2, HID, DIM, 1);
    cudaEventRecord(ev2, s2);

    // main branch: routing
    k_gate<<<N_TOK / 8, 256>>>(x, Wg, bg);
    k_scanscatter<<<1, 256>>>();
    k_gather<<<NSLOT, 128>>>(x);

    // join W1, then GEMM1
    cudaStreamWaitEvent(0, ev1, 0);
    k_gemm<DIM, true><<<dim3(HID / 128, MAX_TILES), 128, SMEM_BYTES>>>(b1, out);
    // join W2 (+ memset), then GEMM2 (fused combine via atomics)
    cudaStreamWaitEvent(0, ev2, 0);
    k_gemm<HID, false><<<dim3(DIM / 128, MAX_TILES), 128, SMEM_BYTES>>>(b2, out);
}